// round 12
// baseline (speedup 1.0000x reference)
#include <cuda_runtime.h>
#include <cuda_bf16.h>
#include <math.h>

#define H_  80
#define W_  80
#define HW  6400
#define C_  256
#define CP  19
#define KS  7
#define K2  49

// Scratch (allocation-free: __device__ globals)
__device__ float g_bias[C_];           // BN-folded bias for w_feat
__device__ float g_wa1[C_ * C_];       // fragment-ordered BN-folded w_feat
__device__ float g_wa2[C_ * C_];       // fragment-ordered w_fuse
__device__ unsigned g_msgpk[128 * HW]; // messages, bf16x2 channel pairs
__device__ float g_agg[C_ * HW];       // aggregated (fp32)
__device__ float g_aff[K2 * HW];       // unnormalized affinity exp(exp(-d/denom))

// ---------------------------------------------------------------------------
// Front kernel: blockIdx-partitioned union of
//   [0,140)      affinity taps (20 x 7 layout, 160 thr = 40 px * 4 rows)
//   [140,1164)   weight rearrange (BN scale folded into w_feat)
//   [1164,1420)  BN-folded bias reduction
// Fragment order: [kb 0..31][mb 0..15][lane][a0..a3].
// ---------------------------------------------------------------------------
__global__ void __launch_bounds__(160) front_kernel(
        const float* __restrict__ coarse, const float* __restrict__ sigma,
        const float* __restrict__ wfeat,  const float* __restrict__ wfuse,
        const float* __restrict__ gamma,  const float* __restrict__ beta,
        const float* __restrict__ mean,   const float* __restrict__ var) {
    int b = blockIdx.x;
    int t = threadIdx.x;

    if (b < 140) {
        // ---- affinity: 2 pixels per thread, sliding window ----
        int tx = t % 40;                  // 0..39 -> pixels 2tx, 2tx+1
        int h  = (b % 20) * 4 + t / 40;
        int i  = b / 20;                  // tap row 0..6
        int b0 = tx * 2;

        float sr = fmaxf(sigma[0], 0.0f);
        float invd = 1.0f / (2.0f * sr * sr + 1e-8f);

        int hh = h + i - 3;
        bool rowok = (hh >= 0) && (hh < H_);
        const float* crow = coarse + h * W_;
        const float* nrow = coarse + (rowok ? hh : 0) * W_;

        bool v[5];
#pragma unroll
        for (int l = 0; l < 5; l++) {
            int col = b0 - 4 + 2 * l;
            v[l] = rowok && (col >= 0) && (col <= W_ - 2);
        }

        float d[KS][2];
#pragma unroll
        for (int j = 0; j < KS; j++) { d[j][0] = 0.0f; d[j][1] = 0.0f; }

        const float2 z2 = make_float2(0.0f, 0.0f);
#pragma unroll
        for (int cp = 0; cp < CP; cp++) {
            float2 cen = *(const float2*)(crow + cp * HW + b0);
            const float* nb = nrow + cp * HW;
            float win[8];
            float2 L;
            L = v[0] ? *(const float2*)(nb + b0 - 4) : z2; win[0] = L.y;
            L = v[1] ? *(const float2*)(nb + b0 - 2) : z2; win[1] = L.x; win[2] = L.y;
            L = v[2] ? *(const float2*)(nb + b0)     : z2; win[3] = L.x; win[4] = L.y;
            L = v[3] ? *(const float2*)(nb + b0 + 2) : z2; win[5] = L.x; win[6] = L.y;
            L = v[4] ? *(const float2*)(nb + b0 + 4) : z2; win[7] = L.x;
#pragma unroll
            for (int j = 0; j < KS; j++) {
                float t0 = win[j]     - cen.x; d[j][0] += t0 * t0;
                float t1 = win[j + 1] - cen.y; d[j][1] += t1 * t1;
            }
        }

        int p = h * W_ + b0;
#pragma unroll
        for (int j = 0; j < KS; j++) {
            g_aff[(i * KS + j) * HW + p]     = __expf(__expf(-d[j][0] * invd));
            g_aff[(i * KS + j) * HW + p + 1] = __expf(__expf(-d[j][1] * invd));
        }
    } else if (b < 1164) {
        // ---- weight rearrange ----
        if (t < 128) {
            int bb = b - 140;
            int w2 = bb >> 9;             // 0: wfeat (scaled), 1: wfuse
            bb &= 511;
            int kb = bb & 31, mb = bb >> 5;
            int lane = t & 31, q = t >> 5;
            int gid = lane >> 2, tig = lane & 3;
            int row = mb * 16 + gid + (q & 1) * 8;
            int col = kb * 8 + tig + (q >> 1) * 4;
            const float* src = w2 ? wfuse : wfeat;
            float v = src[row * C_ + col];
            if (!w2) v *= gamma[col] * rsqrtf(var[col] + 1e-5f);
            float* dst = w2 ? g_wa2 : g_wa1;
            dst[((kb * 16 + mb) * 32 + lane) * 4 + q] = v;
        }
    } else {
        // ---- bias reduction ----
        int o = b - 1164;                 // 0..255
        float s = 0.0f;
        for (int c = t; c < C_; c += 160) {
            float a = gamma[c] * rsqrtf(var[c] + 1e-5f);
            s += wfeat[o * C_ + c] * (beta[c] - mean[c] * a);
        }
#pragma unroll
        for (int off = 16; off; off >>= 1) s += __shfl_xor_sync(~0u, s, off);
        __shared__ float red[5];
        if ((t & 31) == 0) red[t >> 5] = s;
        __syncthreads();
        if (t == 0) g_bias[o] = red[0] + red[1] + red[2] + red[3] + red[4];
    }
}

// ---------------------------------------------------------------------------
// Tensor-core GEMM (tf32 mma.sync), BARRIER-FREE MAINLOOP.
// Tile 128x64. The block's full B panel [K=256][64] is cp.async'd into
// dynamic smem ONCE (one wait + one syncthreads); the 32 k8-steps then run
// with no synchronization at all — warps slip freely to hide LDG/LDS latency.
// 8 warps (2x4), warp tile 64x16 (4 mi x 2 ni frags). Grid 100x2.
// ---------------------------------------------------------------------------
#define GBN 64
#define BSTR (GBN + 8)      // 72: LDS frag bank = 8*tig+gid, conflict-free
#define BPANEL_BYTES (C_ * BSTR * 4)   // 73728

__device__ __forceinline__ void cp16(void* smem, const void* gmem) {
    unsigned s = (unsigned)__cvta_generic_to_shared(smem);
    asm volatile("cp.async.ca.shared.global [%0], [%1], 16;\n" :: "r"(s), "l"(gmem));
}

__device__ __forceinline__ void mma_tf32(float* c, const unsigned* a, const unsigned* b) {
    asm volatile(
        "mma.sync.aligned.m16n8k8.row.col.f32.tf32.tf32.f32 "
        "{%0,%1,%2,%3}, {%4,%5,%6,%7}, {%8,%9}, {%0,%1,%2,%3};\n"
        : "+f"(c[0]), "+f"(c[1]), "+f"(c[2]), "+f"(c[3])
        : "r"(a[0]), "r"(a[1]), "r"(a[2]), "r"(a[3]), "r"(b[0]), "r"(b[1]));
}

__global__ void __launch_bounds__(256) gemm_tc(
        const float* __restrict__ Afrag,   // fragment-ordered [32][16][32][4]
        const float* __restrict__ B,       // [C_ x HW]
        float* __restrict__ Cout,          // used when msgpk == null
        unsigned* __restrict__ msgpk,      // packed output (or null)
        const float* __restrict__ bias,
        const float* __restrict__ resid) {
    extern __shared__ __align__(16) float Bs_raw[];
    float (*Bs)[BSTR] = (float(*)[BSTR])Bs_raw;
    const int N = HW;

    int t    = threadIdx.x;
    int warp = t >> 5, lane = t & 31;
    int gid  = lane >> 2, tig = lane & 3;
    int wm   = warp >> 2, wn = warp & 3;      // 2 x 4 warps
    int m0   = blockIdx.y * 128, n0 = blockIdx.x * GBN;
    int mbw  = (m0 >> 4) + wm * 4;            // warp's base 16-row block

    // ---- one-shot B panel load: 256 rows x 64 cols = 4096 16B chunks ----
#pragma unroll
    for (int i = 0; i < 16; i++) {
        int c = t + 256 * i;
        int row = c >> 4, cq = (c & 15) * 4;
        cp16(&Bs[row][cq], B + row * N + n0 + cq);
    }
    asm volatile("cp.async.commit_group;\n");

    float acc[4][2][4];
#pragma unroll
    for (int mi = 0; mi < 4; mi++)
#pragma unroll
        for (int ni = 0; ni < 2; ni++)
#pragma unroll
            for (int q = 0; q < 4; q++) acc[mi][ni][q] = 0.0f;

    asm volatile("cp.async.wait_group 0;\n");
    __syncthreads();
    // ---- mainloop: 32 k8-steps, NO barriers ----
    const float* abase = Afrag + lane * 4;
    int cN0 = wn * 16 + gid;
#pragma unroll 4
    for (int ks = 0; ks < 32; ks++) {
        unsigned aR[4][4];
#pragma unroll
        for (int mi = 0; mi < 4; mi++) {
            float4 a = *(const float4*)(abase + (ks * 16 + mbw + mi) * 128);
            aR[mi][0] = __float_as_uint(a.x);
            aR[mi][1] = __float_as_uint(a.y);
            aR[mi][2] = __float_as_uint(a.z);
            aR[mi][3] = __float_as_uint(a.w);
        }
        unsigned bR[2][2];
#pragma unroll
        for (int ni = 0; ni < 2; ni++) {
            bR[ni][0] = __float_as_uint(Bs[ks * 8 + tig][cN0 + ni * 8]);
            bR[ni][1] = __float_as_uint(Bs[ks * 8 + tig + 4][cN0 + ni * 8]);
        }
#pragma unroll
        for (int mi = 0; mi < 4; mi++)
#pragma unroll
            for (int ni = 0; ni < 2; ni++)
                mma_tf32(acc[mi][ni], aR[mi], bR[ni]);
    }

    // ---- epilogue ----
#pragma unroll
    for (int mi = 0; mi < 4; mi++) {
        int r0 = (mbw + mi) * 16 + gid;
        int r1 = r0 + 8;
        float b0v = bias ? bias[r0] : 0.0f;
        float b1v = bias ? bias[r1] : 0.0f;
#pragma unroll
        for (int ni = 0; ni < 2; ni++) {
            int col = n0 + wn * 16 + ni * 8 + tig * 2;
            float2 v0, v1;
            v0.x = acc[mi][ni][0] + b0v;
            v0.y = acc[mi][ni][1] + b0v;
            v1.x = acc[mi][ni][2] + b1v;
            v1.y = acc[mi][ni][3] + b1v;
            if (msgpk) {
                int pid = (mbw + mi) * 8 + gid;   // pairs rows (r0, r0+8)
                __nv_bfloat162 w0 = __floats2bfloat162_rn(v0.x, v1.x);
                __nv_bfloat162 w1 = __floats2bfloat162_rn(v0.y, v1.y);
                uint2 pk;
                pk.x = *reinterpret_cast<unsigned*>(&w0);
                pk.y = *reinterpret_cast<unsigned*>(&w1);
                *(uint2*)(msgpk + pid * N + col) = pk;
            } else {
                if (resid) {
                    float2 rv0 = *(const float2*)(resid + r0 * N + col);
                    float2 rv1 = *(const float2*)(resid + r1 * N + col);
                    v0.x += rv0.x; v0.y += rv0.y;
                    v1.x += rv1.x; v1.y += rv1.y;
                }
                *(float2*)(Cout + r0 * N + col) = v0;
                *(float2*)(Cout + r1 * N + col) = v1;
            }
        }
    }
}

// ---------------------------------------------------------------------------
// Aggregation: 4 pixels x 2 channel-pairs per thread.
// Block (20,16)=320 thr, grid (80,4). bf16x2 unpack is exact (<<16).
// ---------------------------------------------------------------------------
__global__ void __launch_bounds__(320) agg_kernel() {
    int h  = blockIdx.x;                       // 0..79
    int tx = threadIdx.x;                      // 0..19 -> pixels 4tx..4tx+3
    int ty = threadIdx.y;                      // 0..15
    int pbase = blockIdx.y * 32 + ty * 2;      // 2 pairs per thread

    __shared__ __align__(16) float saff[K2][W_];
    __shared__ __align__(16) float sinv[W_];
    int tid = ty * 20 + tx;
    const float* affrow = g_aff + h * W_;
    for (int idx = tid; idx < K2 * W_; idx += 320) {
        int k2 = idx / W_;
        int ww = idx - k2 * W_;
        saff[k2][ww] = affrow[k2 * HW + ww];
    }
    __syncthreads();
    if (tid < W_) {
        float s = 0.0f;
#pragma unroll
        for (int k = 0; k < K2; k++) s += saff[k][tid];
        sinv[tid] = 1.0f / s;
    }
    __syncthreads();

    float2 acc[4][2];   // [px][pair]: x = low channel, y = high channel
#pragma unroll
    for (int px = 0; px < 4; px++)
#pragma unroll
        for (int pr = 0; pr < 2; pr++) acc[px][pr] = make_float2(0.f, 0.f);

    const uint4 z4 = make_uint4(0u, 0u, 0u, 0u);
    bool haveA = (tx > 0), haveC = (tx < 19);

    for (int i = 0; i < KS; i++) {
        int hh = h + i - 3;
        if (hh < 0 || hh >= H_) continue;

        float4 s[KS];
#pragma unroll
        for (int j = 0; j < KS; j++)
            s[j] = *(const float4*)&saff[i * KS + j][tx * 4];

#pragma unroll
        for (int pr = 0; pr < 2; pr++) {
            const unsigned* mrow = g_msgpk + (pbase + pr) * HW + hh * W_;
            uint4 va = haveA ? *(const uint4*)(mrow + tx * 4 - 4) : z4;
            uint4 vb = *(const uint4*)(mrow + tx * 4);
            uint4 vc = haveC ? *(const uint4*)(mrow + tx * 4 + 4) : z4;
            unsigned wd[10] = {va.y, va.z, va.w,
                               vb.x, vb.y, vb.z, vb.w,
                               vc.x, vc.y, vc.z};
            float wl[10], wh[10];
#pragma unroll
            for (int q = 0; q < 10; q++) {
                wl[q] = __uint_as_float(wd[q] << 16);
                wh[q] = __uint_as_float(wd[q] & 0xFFFF0000u);
            }
#pragma unroll
            for (int j = 0; j < KS; j++) {
                acc[0][pr].x += wl[j + 0] * s[j].x;
                acc[0][pr].y += wh[j + 0] * s[j].x;
                acc[1][pr].x += wl[j + 1] * s[j].y;
                acc[1][pr].y += wh[j + 1] * s[j].y;
                acc[2][pr].x += wl[j + 2] * s[j].z;
                acc[2][pr].y += wh[j + 2] * s[j].z;
                acc[3][pr].x += wl[j + 3] * s[j].w;
                acc[3][pr].y += wh[j + 3] * s[j].w;
            }
        }
    }

    float4 si = *(const float4*)&sinv[tx * 4];
#pragma unroll
    for (int pr = 0; pr < 2; pr++) {
        int pid = pbase + pr;
        int c0 = (pid >> 3) * 16 + (pid & 7);
        int c1 = c0 + 8;
        float4 lo = make_float4(acc[0][pr].x * si.x, acc[1][pr].x * si.y,
                                acc[2][pr].x * si.z, acc[3][pr].x * si.w);
        float4 hi = make_float4(acc[0][pr].y * si.x, acc[1][pr].y * si.y,
                                acc[2][pr].y * si.z, acc[3][pr].y * si.w);
        *(float4*)(g_agg + c0 * HW + h * W_ + tx * 4) = lo;
        *(float4*)(g_agg + c1 * HW + h * W_ + tx * 4) = hi;
    }
}

// ---------------------------------------------------------------------------
// Launch
// ---------------------------------------------------------------------------
extern "C" void kernel_launch(void* const* d_in, const int* in_sizes, int n_in,
                              void* d_out, int out_size) {
    const float* x      = (const float*)d_in[0];
    const float* coarse = (const float*)d_in[1];
    const float* sigma  = (const float*)d_in[2];
    const float* wfeat  = (const float*)d_in[3];
    const float* wfuse  = (const float*)d_in[4];
    const float* gamma  = (const float*)d_in[5];
    const float* beta   = (const float*)d_in[6];
    const float* mean   = (const float*)d_in[7];
    const float* var    = (const float*)d_in[8];
    float* out = (float*)d_out;

    float *wa1, *wa2, *bias, *agg;
    unsigned* msgpk;
    cudaGetSymbolAddress((void**)&wa1,   g_wa1);
    cudaGetSymbolAddress((void**)&wa2,   g_wa2);
    cudaGetSymbolAddress((void**)&bias,  g_bias);
    cudaGetSymbolAddress((void**)&msgpk, g_msgpk);
    cudaGetSymbolAddress((void**)&agg,   g_agg);

    cudaFuncSetAttribute(gemm_tc,
        cudaFuncAttributeMaxDynamicSharedMemorySize, BPANEL_BYTES);

    // affinity taps + weight rearrange + bias, one launch
    front_kernel<<<1420, 160>>>(coarse, sigma, wfeat, wfuse,
                                gamma, beta, mean, var);
    // messages = w' @ x + bias  (packed bf16x2 channel-pair output)
    gemm_tc<<<dim3(HW / GBN, 2), 256, BPANEL_BYTES>>>(
        wa1, x, nullptr, msgpk, bias, nullptr);
    // spatially-varying 7x7 aggregation with fused softmax normalization
    agg_kernel<<<dim3(H_, C_ / 64), dim3(20, 16)>>>();
    // out = x + w_fuse @ agg
    gemm_tc<<<dim3(HW / GBN, 2), 256, BPANEL_BYTES>>>(
        wa2, agg, out, nullptr, nullptr, x);
}

// round 13
// speedup vs baseline: 1.0031x; 1.0031x over previous
#include <cuda_runtime.h>
#include <cuda_bf16.h>
#include <math.h>

#define H_  80
#define W_  80
#define HW  6400
#define C_  256
#define CP  19
#define KS  7
#define K2  49

// Scratch (allocation-free: __device__ globals)
__device__ float g_bias[C_];           // BN-folded bias for w_feat
__device__ float g_wa1[C_ * C_];       // fragment-ordered BN-folded w_feat
__device__ float g_wa2[C_ * C_];       // fragment-ordered w_fuse
__device__ unsigned g_msgpk[128 * HW]; // messages, bf16x2 channel pairs
__device__ float g_agg[C_ * HW];       // aggregated (fp32)
__device__ float g_aff[K2 * HW];       // unnormalized affinity exp(exp(-d/denom))

// ---------------------------------------------------------------------------
// Front kernel: blockIdx-partitioned union of
//   [0,140)      affinity taps (20 x 7 layout, 160 thr = 40 px * 4 rows)
//   [140,1164)   weight rearrange (BN scale folded into w_feat)
//   [1164,1420)  BN-folded bias reduction
// Fragment order: [kb 0..31][mb 0..15][lane][a0..a3].
// ---------------------------------------------------------------------------
__global__ void __launch_bounds__(160) front_kernel(
        const float* __restrict__ coarse, const float* __restrict__ sigma,
        const float* __restrict__ wfeat,  const float* __restrict__ wfuse,
        const float* __restrict__ gamma,  const float* __restrict__ beta,
        const float* __restrict__ mean,   const float* __restrict__ var) {
    int b = blockIdx.x;
    int t = threadIdx.x;

    if (b < 140) {
        // ---- affinity: 2 pixels per thread, sliding window ----
        int tx = t % 40;                  // 0..39 -> pixels 2tx, 2tx+1
        int h  = (b % 20) * 4 + t / 40;
        int i  = b / 20;                  // tap row 0..6
        int b0 = tx * 2;

        float sr = fmaxf(sigma[0], 0.0f);
        float invd = 1.0f / (2.0f * sr * sr + 1e-8f);

        int hh = h + i - 3;
        bool rowok = (hh >= 0) && (hh < H_);
        const float* crow = coarse + h * W_;
        const float* nrow = coarse + (rowok ? hh : 0) * W_;

        bool v[5];
#pragma unroll
        for (int l = 0; l < 5; l++) {
            int col = b0 - 4 + 2 * l;
            v[l] = rowok && (col >= 0) && (col <= W_ - 2);
        }

        float d[KS][2];
#pragma unroll
        for (int j = 0; j < KS; j++) { d[j][0] = 0.0f; d[j][1] = 0.0f; }

        const float2 z2 = make_float2(0.0f, 0.0f);
#pragma unroll
        for (int cp = 0; cp < CP; cp++) {
            float2 cen = *(const float2*)(crow + cp * HW + b0);
            const float* nb = nrow + cp * HW;
            float win[8];
            float2 L;
            L = v[0] ? *(const float2*)(nb + b0 - 4) : z2; win[0] = L.y;
            L = v[1] ? *(const float2*)(nb + b0 - 2) : z2; win[1] = L.x; win[2] = L.y;
            L = v[2] ? *(const float2*)(nb + b0)     : z2; win[3] = L.x; win[4] = L.y;
            L = v[3] ? *(const float2*)(nb + b0 + 2) : z2; win[5] = L.x; win[6] = L.y;
            L = v[4] ? *(const float2*)(nb + b0 + 4) : z2; win[7] = L.x;
#pragma unroll
            for (int j = 0; j < KS; j++) {
                float t0 = win[j]     - cen.x; d[j][0] += t0 * t0;
                float t1 = win[j + 1] - cen.y; d[j][1] += t1 * t1;
            }
        }

        int p = h * W_ + b0;
#pragma unroll
        for (int j = 0; j < KS; j++) {
            g_aff[(i * KS + j) * HW + p]     = __expf(__expf(-d[j][0] * invd));
            g_aff[(i * KS + j) * HW + p + 1] = __expf(__expf(-d[j][1] * invd));
        }
    } else if (b < 1164) {
        // ---- weight rearrange ----
        if (t < 128) {
            int bb = b - 140;
            int w2 = bb >> 9;             // 0: wfeat (scaled), 1: wfuse
            bb &= 511;
            int kb = bb & 31, mb = bb >> 5;
            int lane = t & 31, q = t >> 5;
            int gid = lane >> 2, tig = lane & 3;
            int row = mb * 16 + gid + (q & 1) * 8;
            int col = kb * 8 + tig + (q >> 1) * 4;
            const float* src = w2 ? wfuse : wfeat;
            float v = src[row * C_ + col];
            if (!w2) v *= gamma[col] * rsqrtf(var[col] + 1e-5f);
            float* dst = w2 ? g_wa2 : g_wa1;
            dst[((kb * 16 + mb) * 32 + lane) * 4 + q] = v;
        }
    } else {
        // ---- bias reduction ----
        int o = b - 1164;                 // 0..255
        float s = 0.0f;
        for (int c = t; c < C_; c += 160) {
            float a = gamma[c] * rsqrtf(var[c] + 1e-5f);
            s += wfeat[o * C_ + c] * (beta[c] - mean[c] * a);
        }
#pragma unroll
        for (int off = 16; off; off >>= 1) s += __shfl_xor_sync(~0u, s, off);
        __shared__ float red[5];
        if ((t & 31) == 0) red[t >> 5] = s;
        __syncthreads();
        if (t == 0) g_bias[o] = red[0] + red[1] + red[2] + red[3] + red[4];
    }
}

// ---------------------------------------------------------------------------
// Tensor-core GEMM (tf32 mma.sync), BARRIER-FREE MAINLOOP.
// Tile 128x64. The block's full B panel [K=256][64] is cp.async'd into
// dynamic smem ONCE (one wait + one syncthreads); the 32 k8-steps then run
// with no synchronization at all — warps slip freely to hide LDG/LDS latency.
// 8 warps (2x4), warp tile 64x16 (4 mi x 2 ni frags). Grid 100x2.
// ---------------------------------------------------------------------------
#define GBN 64
#define BSTR (GBN + 8)      // 72: LDS frag bank = 8*tig+gid, conflict-free
#define BPANEL_BYTES (C_ * BSTR * 4)   // 73728

__device__ __forceinline__ void cp16(void* smem, const void* gmem) {
    unsigned s = (unsigned)__cvta_generic_to_shared(smem);
    asm volatile("cp.async.ca.shared.global [%0], [%1], 16;\n" :: "r"(s), "l"(gmem));
}

__device__ __forceinline__ void mma_tf32(float* c, const unsigned* a, const unsigned* b) {
    asm volatile(
        "mma.sync.aligned.m16n8k8.row.col.f32.tf32.tf32.f32 "
        "{%0,%1,%2,%3}, {%4,%5,%6,%7}, {%8,%9}, {%0,%1,%2,%3};\n"
        : "+f"(c[0]), "+f"(c[1]), "+f"(c[2]), "+f"(c[3])
        : "r"(a[0]), "r"(a[1]), "r"(a[2]), "r"(a[3]), "r"(b[0]), "r"(b[1]));
}

__global__ void __launch_bounds__(256) gemm_tc(
        const float* __restrict__ Afrag,   // fragment-ordered [32][16][32][4]
        const float* __restrict__ B,       // [C_ x HW]
        float* __restrict__ Cout,          // used when msgpk == null
        unsigned* __restrict__ msgpk,      // packed output (or null)
        const float* __restrict__ bias,
        const float* __restrict__ resid) {
    extern __shared__ __align__(16) float Bs_raw[];
    float (*Bs)[BSTR] = (float(*)[BSTR])Bs_raw;
    const int N = HW;

    int t    = threadIdx.x;
    int warp = t >> 5, lane = t & 31;
    int gid  = lane >> 2, tig = lane & 3;
    int wm   = warp >> 2, wn = warp & 3;      // 2 x 4 warps
    int m0   = blockIdx.y * 128, n0 = blockIdx.x * GBN;
    int mbw  = (m0 >> 4) + wm * 4;            // warp's base 16-row block

    // ---- one-shot B panel load: 256 rows x 64 cols = 4096 16B chunks ----
#pragma unroll
    for (int i = 0; i < 16; i++) {
        int c = t + 256 * i;
        int row = c >> 4, cq = (c & 15) * 4;
        cp16(&Bs[row][cq], B + row * N + n0 + cq);
    }
    asm volatile("cp.async.commit_group;\n");

    float acc[4][2][4];
#pragma unroll
    for (int mi = 0; mi < 4; mi++)
#pragma unroll
        for (int ni = 0; ni < 2; ni++)
#pragma unroll
            for (int q = 0; q < 4; q++) acc[mi][ni][q] = 0.0f;

    asm volatile("cp.async.wait_group 0;\n");
    __syncthreads();
    // ---- mainloop: 32 k8-steps, NO barriers ----
    const float* abase = Afrag + lane * 4;
    int cN0 = wn * 16 + gid;
#pragma unroll 4
    for (int ks = 0; ks < 32; ks++) {
        unsigned aR[4][4];
#pragma unroll
        for (int mi = 0; mi < 4; mi++) {
            float4 a = *(const float4*)(abase + (ks * 16 + mbw + mi) * 128);
            aR[mi][0] = __float_as_uint(a.x);
            aR[mi][1] = __float_as_uint(a.y);
            aR[mi][2] = __float_as_uint(a.z);
            aR[mi][3] = __float_as_uint(a.w);
        }
        unsigned bR[2][2];
#pragma unroll
        for (int ni = 0; ni < 2; ni++) {
            bR[ni][0] = __float_as_uint(Bs[ks * 8 + tig][cN0 + ni * 8]);
            bR[ni][1] = __float_as_uint(Bs[ks * 8 + tig + 4][cN0 + ni * 8]);
        }
#pragma unroll
        for (int mi = 0; mi < 4; mi++)
#pragma unroll
            for (int ni = 0; ni < 2; ni++)
                mma_tf32(acc[mi][ni], aR[mi], bR[ni]);
    }

    // ---- epilogue ----
#pragma unroll
    for (int mi = 0; mi < 4; mi++) {
        int r0 = (mbw + mi) * 16 + gid;
        int r1 = r0 + 8;
        float b0v = bias ? bias[r0] : 0.0f;
        float b1v = bias ? bias[r1] : 0.0f;
#pragma unroll
        for (int ni = 0; ni < 2; ni++) {
            int col = n0 + wn * 16 + ni * 8 + tig * 2;
            float2 v0, v1;
            v0.x = acc[mi][ni][0] + b0v;
            v0.y = acc[mi][ni][1] + b0v;
            v1.x = acc[mi][ni][2] + b1v;
            v1.y = acc[mi][ni][3] + b1v;
            if (msgpk) {
                int pid = (mbw + mi) * 8 + gid;   // pairs rows (r0, r0+8)
                __nv_bfloat162 w0 = __floats2bfloat162_rn(v0.x, v1.x);
                __nv_bfloat162 w1 = __floats2bfloat162_rn(v0.y, v1.y);
                uint2 pk;
                pk.x = *reinterpret_cast<unsigned*>(&w0);
                pk.y = *reinterpret_cast<unsigned*>(&w1);
                *(uint2*)(msgpk + pid * N + col) = pk;
            } else {
                if (resid) {
                    float2 rv0 = *(const float2*)(resid + r0 * N + col);
                    float2 rv1 = *(const float2*)(resid + r1 * N + col);
                    v0.x += rv0.x; v0.y += rv0.y;
                    v1.x += rv1.x; v1.y += rv1.y;
                }
                *(float2*)(Cout + r0 * N + col) = v0;
                *(float2*)(Cout + r1 * N + col) = v1;
            }
        }
    }
}

// ---------------------------------------------------------------------------
// Aggregation: 4 pixels x 2 channel-pairs per thread.
// Block (20,16)=320 thr, grid (80,4). bf16x2 unpack is exact (<<16).
// ---------------------------------------------------------------------------
__global__ void __launch_bounds__(320) agg_kernel() {
    int h  = blockIdx.x;                       // 0..79
    int tx = threadIdx.x;                      // 0..19 -> pixels 4tx..4tx+3
    int ty = threadIdx.y;                      // 0..15
    int pbase = blockIdx.y * 32 + ty * 2;      // 2 pairs per thread

    __shared__ __align__(16) float saff[K2][W_];
    __shared__ __align__(16) float sinv[W_];
    int tid = ty * 20 + tx;
    const float* affrow = g_aff + h * W_;
    for (int idx = tid; idx < K2 * W_; idx += 320) {
        int k2 = idx / W_;
        int ww = idx - k2 * W_;
        saff[k2][ww] = affrow[k2 * HW + ww];
    }
    __syncthreads();
    if (tid < W_) {
        float s = 0.0f;
#pragma unroll
        for (int k = 0; k < K2; k++) s += saff[k][tid];
        sinv[tid] = 1.0f / s;
    }
    __syncthreads();

    float2 acc[4][2];   // [px][pair]: x = low channel, y = high channel
#pragma unroll
    for (int px = 0; px < 4; px++)
#pragma unroll
        for (int pr = 0; pr < 2; pr++) acc[px][pr] = make_float2(0.f, 0.f);

    const uint4 z4 = make_uint4(0u, 0u, 0u, 0u);
    bool haveA = (tx > 0), haveC = (tx < 19);

    for (int i = 0; i < KS; i++) {
        int hh = h + i - 3;
        if (hh < 0 || hh >= H_) continue;

        float4 s[KS];
#pragma unroll
        for (int j = 0; j < KS; j++)
            s[j] = *(const float4*)&saff[i * KS + j][tx * 4];

#pragma unroll
        for (int pr = 0; pr < 2; pr++) {
            const unsigned* mrow = g_msgpk + (pbase + pr) * HW + hh * W_;
            uint4 va = haveA ? *(const uint4*)(mrow + tx * 4 - 4) : z4;
            uint4 vb = *(const uint4*)(mrow + tx * 4);
            uint4 vc = haveC ? *(const uint4*)(mrow + tx * 4 + 4) : z4;
            unsigned wd[10] = {va.y, va.z, va.w,
                               vb.x, vb.y, vb.z, vb.w,
                               vc.x, vc.y, vc.z};
            float wl[10], wh[10];
#pragma unroll
            for (int q = 0; q < 10; q++) {
                wl[q] = __uint_as_float(wd[q] << 16);
                wh[q] = __uint_as_float(wd[q] & 0xFFFF0000u);
            }
#pragma unroll
            for (int j = 0; j < KS; j++) {
                acc[0][pr].x += wl[j + 0] * s[j].x;
                acc[0][pr].y += wh[j + 0] * s[j].x;
                acc[1][pr].x += wl[j + 1] * s[j].y;
                acc[1][pr].y += wh[j + 1] * s[j].y;
                acc[2][pr].x += wl[j + 2] * s[j].z;
                acc[2][pr].y += wh[j + 2] * s[j].z;
                acc[3][pr].x += wl[j + 3] * s[j].w;
                acc[3][pr].y += wh[j + 3] * s[j].w;
            }
        }
    }

    float4 si = *(const float4*)&sinv[tx * 4];
#pragma unroll
    for (int pr = 0; pr < 2; pr++) {
        int pid = pbase + pr;
        int c0 = (pid >> 3) * 16 + (pid & 7);
        int c1 = c0 + 8;
        float4 lo = make_float4(acc[0][pr].x * si.x, acc[1][pr].x * si.y,
                                acc[2][pr].x * si.z, acc[3][pr].x * si.w);
        float4 hi = make_float4(acc[0][pr].y * si.x, acc[1][pr].y * si.y,
                                acc[2][pr].y * si.z, acc[3][pr].y * si.w);
        *(float4*)(g_agg + c0 * HW + h * W_ + tx * 4) = lo;
        *(float4*)(g_agg + c1 * HW + h * W_ + tx * 4) = hi;
    }
}

// ---------------------------------------------------------------------------
// Launch
// ---------------------------------------------------------------------------
extern "C" void kernel_launch(void* const* d_in, const int* in_sizes, int n_in,
                              void* d_out, int out_size) {
    const float* x      = (const float*)d_in[0];
    const float* coarse = (const float*)d_in[1];
    const float* sigma  = (const float*)d_in[2];
    const float* wfeat  = (const float*)d_in[3];
    const float* wfuse  = (const float*)d_in[4];
    const float* gamma  = (const float*)d_in[5];
    const float* beta   = (const float*)d_in[6];
    const float* mean   = (const float*)d_in[7];
    const float* var    = (const float*)d_in[8];
    float* out = (float*)d_out;

    float *wa1, *wa2, *bias, *agg;
    unsigned* msgpk;
    cudaGetSymbolAddress((void**)&wa1,   g_wa1);
    cudaGetSymbolAddress((void**)&wa2,   g_wa2);
    cudaGetSymbolAddress((void**)&bias,  g_bias);
    cudaGetSymbolAddress((void**)&msgpk, g_msgpk);
    cudaGetSymbolAddress((void**)&agg,   g_agg);

    cudaFuncSetAttribute(gemm_tc,
        cudaFuncAttributeMaxDynamicSharedMemorySize, BPANEL_BYTES);

    // affinity taps + weight rearrange + bias, one launch
    front_kernel<<<1420, 160>>>(coarse, sigma, wfeat, wfuse,
                                gamma, beta, mean, var);
    // messages = w' @ x + bias  (packed bf16x2 channel-pair output)
    gemm_tc<<<dim3(HW / GBN, 2), 256, BPANEL_BYTES>>>(
        wa1, x, nullptr, msgpk, bias, nullptr);
    // spatially-varying 7x7 aggregation with fused softmax normalization
    agg_kernel<<<dim3(H_, C_ / 64), dim3(20, 16)>>>();
    // out = x + w_fuse @ agg
    gemm_tc<<<dim3(HW / GBN, 2), 256, BPANEL_BYTES>>>(
        wa2, agg, out, nullptr, nullptr, x);
}

// round 14
// speedup vs baseline: 1.8103x; 1.8046x over previous
#include <cuda_runtime.h>
#include <cuda_bf16.h>
#include <math.h>

#define H_  80
#define W_  80
#define HW  6400
#define C_  256
#define CP  19
#define KS  7
#define K2  49

// Scratch (allocation-free: __device__ globals)
__device__ float g_bias[C_];           // BN-folded bias for w_feat
__device__ float g_wa1[C_ * C_];       // fragment-ordered BN-folded w_feat
__device__ float g_wa2[C_ * C_];       // fragment-ordered w_fuse
__device__ unsigned g_msgpk[128 * HW]; // messages, bf16x2 channel pairs
__device__ float g_agg[C_ * HW];       // aggregated (fp32)
__device__ float g_aff[K2 * HW];       // unnormalized affinity exp(exp(-d/denom))

// ---------------------------------------------------------------------------
// setup: weight rearrange (BN scale folded into w_feat) + BN-folded bias.
//   [0,1024)     rearrange (t<128 active)
//   [1024,1280)  bias reduction
// Fragment order: [kb 0..31][mb 0..15][lane][a0..a3].
// ---------------------------------------------------------------------------
__global__ void __launch_bounds__(160) setup_kernel(
        const float* __restrict__ wfeat,  const float* __restrict__ wfuse,
        const float* __restrict__ gamma,  const float* __restrict__ beta,
        const float* __restrict__ mean,   const float* __restrict__ var) {
    int b = blockIdx.x;
    int t = threadIdx.x;
    if (b < 1024) {
        if (t < 128) {
            int w2 = b >> 9;              // 0: wfeat (scaled), 1: wfuse
            int bb = b & 511;
            int kb = bb & 31, mb = bb >> 5;
            int lane = t & 31, q = t >> 5;
            int gid = lane >> 2, tig = lane & 3;
            int row = mb * 16 + gid + (q & 1) * 8;
            int col = kb * 8 + tig + (q >> 1) * 4;
            const float* src = w2 ? wfuse : wfeat;
            float v = src[row * C_ + col];
            if (!w2) v *= gamma[col] * rsqrtf(var[col] + 1e-5f);
            float* dst = w2 ? g_wa2 : g_wa1;
            dst[((kb * 16 + mb) * 32 + lane) * 4 + q] = v;
        }
    } else {
        int o = b - 1024;                 // 0..255
        float s = 0.0f;
        for (int c = t; c < C_; c += 160) {
            float a = gamma[c] * rsqrtf(var[c] + 1e-5f);
            s += wfeat[o * C_ + c] * (beta[c] - mean[c] * a);
        }
#pragma unroll
        for (int off = 16; off; off >>= 1) s += __shfl_xor_sync(~0u, s, off);
        __shared__ float red[5];
        if ((t & 31) == 0) red[t >> 5] = s;
        __syncthreads();
        if (t == 0) g_bias[o] = red[0] + red[1] + red[2] + red[3] + red[4];
    }
}

// ---------------------------------------------------------------------------
// GEMM body (R8-proven config): tf32 mma.sync, A-frags via LDG from arranged
// buffer, B via 3-stage cp.async. Tile 64x64, BK=32, 8 warps (2x4), warp
// 32x16. Epilogue: packed bf16x2 channel-pairs (msgpk) or fp32 (+resid).
// ---------------------------------------------------------------------------
#define GBM 64
#define GBN 64
#define GBK 32
#define BSTR (GBN + 8)
#define NSTG 3

__device__ __forceinline__ void cp16(void* smem, const void* gmem) {
    unsigned s = (unsigned)__cvta_generic_to_shared(smem);
    asm volatile("cp.async.ca.shared.global [%0], [%1], 16;\n" :: "r"(s), "l"(gmem));
}

__device__ __forceinline__ void mma_tf32(float* c, const unsigned* a, const unsigned* b) {
    asm volatile(
        "mma.sync.aligned.m16n8k8.row.col.f32.tf32.tf32.f32 "
        "{%0,%1,%2,%3}, {%4,%5,%6,%7}, {%8,%9}, {%0,%1,%2,%3};\n"
        : "+f"(c[0]), "+f"(c[1]), "+f"(c[2]), "+f"(c[3])
        : "r"(a[0]), "r"(a[1]), "r"(a[2]), "r"(a[3]), "r"(b[0]), "r"(b[1]));
}

__device__ __forceinline__ void gemm_body(
        int bx, int by,
        const float* __restrict__ Afrag,
        const float* __restrict__ B,
        float* __restrict__ Cout,
        unsigned* __restrict__ msgpk,
        const float* __restrict__ bias,
        const float* __restrict__ resid) {
    __shared__ __align__(16) float Bs[NSTG][GBK][BSTR];
    const int N = HW;

    int t    = threadIdx.x;
    int warp = t >> 5, lane = t & 31;
    int gid  = lane >> 2, tig = lane & 3;
    int wm   = warp >> 2, wn = warp & 3;
    int m0   = by * GBM, n0 = bx * GBN;
    int mb0  = by * 4 + wm * 2;

    int kr0 = t >> 4;
    int co  = (t & 15) * 4;

    float acc[2][2][4];
#pragma unroll
    for (int mi = 0; mi < 2; mi++)
#pragma unroll
        for (int ni = 0; ni < 2; ni++)
#pragma unroll
            for (int q = 0; q < 4; q++) acc[mi][ni][q] = 0.0f;

#define LOADB(s, k0)                                                          \
    {                                                                          \
        cp16(&Bs[s][kr0][co],      B + ((k0) + kr0) * N + n0 + co);            \
        cp16(&Bs[s][kr0 + 16][co], B + ((k0) + kr0 + 16) * N + n0 + co);       \
        asm volatile("cp.async.commit_group;\n");                              \
    }

    LOADB(0, 0);
    LOADB(1, GBK);

    const int NIT = C_ / GBK;   // 8
    for (int it = 0; it < NIT; it++) {
        if (it + 1 < NIT) asm volatile("cp.async.wait_group 1;\n");
        else              asm volatile("cp.async.wait_group 0;\n");
        __syncthreads();
        if (it + 2 < NIT) LOADB((it + 2) % NSTG, (it + 2) * GBK);

        int s = it % NSTG;
#pragma unroll
        for (int kk = 0; kk < GBK / 8; kk++) {
            int kbg = it * 4 + kk;
            float4 a0 = *(const float4*)(Afrag + ((kbg * 16 + mb0) * 32 + lane) * 4);
            float4 a1 = *(const float4*)(Afrag + ((kbg * 16 + mb0 + 1) * 32 + lane) * 4);
            unsigned aR[2][4];
            aR[0][0] = __float_as_uint(a0.x); aR[0][1] = __float_as_uint(a0.y);
            aR[0][2] = __float_as_uint(a0.z); aR[0][3] = __float_as_uint(a0.w);
            aR[1][0] = __float_as_uint(a1.x); aR[1][1] = __float_as_uint(a1.y);
            aR[1][2] = __float_as_uint(a1.z); aR[1][3] = __float_as_uint(a1.w);

            unsigned bR[2][2];
#pragma unroll
            for (int ni = 0; ni < 2; ni++) {
                int cN = wn * 16 + ni * 8 + gid;
                bR[ni][0] = __float_as_uint(Bs[s][kk * 8 + tig][cN]);
                bR[ni][1] = __float_as_uint(Bs[s][kk * 8 + tig + 4][cN]);
            }
#pragma unroll
            for (int mi = 0; mi < 2; mi++)
#pragma unroll
                for (int ni = 0; ni < 2; ni++)
                    mma_tf32(acc[mi][ni], aR[mi], bR[ni]);
        }
        __syncthreads();
    }

#pragma unroll
    for (int mi = 0; mi < 2; mi++) {
        int r0 = m0 + wm * 32 + mi * 16 + gid;
        int r1 = r0 + 8;
        float b0v = bias ? bias[r0] : 0.0f;
        float b1v = bias ? bias[r1] : 0.0f;
#pragma unroll
        for (int ni = 0; ni < 2; ni++) {
            int col = n0 + wn * 16 + ni * 8 + tig * 2;
            float2 v0, v1;
            v0.x = acc[mi][ni][0] + b0v;
            v0.y = acc[mi][ni][1] + b0v;
            v1.x = acc[mi][ni][2] + b1v;
            v1.y = acc[mi][ni][3] + b1v;
            if (msgpk) {
                int pid = ((m0 >> 4) + wm * 2 + mi) * 8 + gid;
                __nv_bfloat162 w0 = __floats2bfloat162_rn(v0.x, v1.x);
                __nv_bfloat162 w1 = __floats2bfloat162_rn(v0.y, v1.y);
                uint2 pk;
                pk.x = *reinterpret_cast<unsigned*>(&w0);
                pk.y = *reinterpret_cast<unsigned*>(&w1);
                *(uint2*)(msgpk + pid * N + col) = pk;
            } else {
                if (resid) {
                    float2 rv0 = *(const float2*)(resid + r0 * N + col);
                    float2 rv1 = *(const float2*)(resid + r1 * N + col);
                    v0.x += rv0.x; v0.y += rv0.y;
                    v1.x += rv1.x; v1.y += rv1.y;
                }
                *(float2*)(Cout + r0 * N + col) = v0;
                *(float2*)(Cout + r1 * N + col) = v1;
            }
        }
    }
#undef LOADB
}

// ---------------------------------------------------------------------------
// Fused GEMM1 + affinity: blocks [0,400) = GEMM tiles (bx=b%100, by=b/100),
// blocks [400,498) = affinity taps (2 px/thread, 6 rows/block, t<240).
// Affinity runs concurrently with GEMM1 (independent data paths).
// ---------------------------------------------------------------------------
__global__ void __launch_bounds__(256) fused_g1_aff_kernel(
        const float* __restrict__ coarse, const float* __restrict__ sigma,
        const float* __restrict__ Afrag,  const float* __restrict__ B,
        unsigned* __restrict__ msgpk,     const float* __restrict__ bias) {
    int b = blockIdx.x;
    if (b < 400) {
        gemm_body(b % 100, b / 100, Afrag, B, nullptr, msgpk, bias, nullptr);
        return;
    }
    // ---- affinity ----
    int t = threadIdx.x;
    if (t >= 240) return;
    int bb = b - 400;                 // 0..97
    int i  = bb / 14;                 // tap row 0..6
    int h  = (bb % 14) * 6 + t / 40;  // 6 rows per block
    if (h >= H_) return;
    int tx = t % 40;                  // pixels 2tx, 2tx+1
    int b0 = tx * 2;

    float sr = fmaxf(sigma[0], 0.0f);
    float invd = 1.0f / (2.0f * sr * sr + 1e-8f);

    int hh = h + i - 3;
    bool rowok = (hh >= 0) && (hh < H_);
    const float* crow = coarse + h * W_;
    const float* nrow = coarse + (rowok ? hh : 0) * W_;

    bool v[5];
#pragma unroll
    for (int l = 0; l < 5; l++) {
        int col = b0 - 4 + 2 * l;
        v[l] = rowok && (col >= 0) && (col <= W_ - 2);
    }

    float d[KS][2];
#pragma unroll
    for (int j = 0; j < KS; j++) { d[j][0] = 0.0f; d[j][1] = 0.0f; }

    const float2 z2 = make_float2(0.0f, 0.0f);
#pragma unroll
    for (int cp = 0; cp < CP; cp++) {
        float2 cen = *(const float2*)(crow + cp * HW + b0);
        const float* nb = nrow + cp * HW;
        float win[8];
        float2 L;
        L = v[0] ? *(const float2*)(nb + b0 - 4) : z2; win[0] = L.y;
        L = v[1] ? *(const float2*)(nb + b0 - 2) : z2; win[1] = L.x; win[2] = L.y;
        L = v[2] ? *(const float2*)(nb + b0)     : z2; win[3] = L.x; win[4] = L.y;
        L = v[3] ? *(const float2*)(nb + b0 + 2) : z2; win[5] = L.x; win[6] = L.y;
        L = v[4] ? *(const float2*)(nb + b0 + 4) : z2; win[7] = L.x;
#pragma unroll
        for (int j = 0; j < KS; j++) {
            float t0 = win[j]     - cen.x; d[j][0] += t0 * t0;
            float t1 = win[j + 1] - cen.y; d[j][1] += t1 * t1;
        }
    }

    int p = h * W_ + b0;
#pragma unroll
    for (int j = 0; j < KS; j++) {
        g_aff[(i * KS + j) * HW + p]     = __expf(__expf(-d[j][0] * invd));
        g_aff[(i * KS + j) * HW + p + 1] = __expf(__expf(-d[j][1] * invd));
    }
}

// GEMM2: standalone wrapper around gemm_body.
__global__ void __launch_bounds__(256) gemm2_kernel(
        const float* __restrict__ Afrag, const float* __restrict__ B,
        float* __restrict__ Cout,        const float* __restrict__ resid) {
    gemm_body(blockIdx.x, blockIdx.y, Afrag, B, Cout, nullptr, nullptr, resid);
}

// ---------------------------------------------------------------------------
// Aggregation: 4 pixels x 2 channel-pairs per thread.
// Block (20,16)=320 thr, grid (80,4). bf16x2 unpack is exact (<<16).
// ---------------------------------------------------------------------------
__global__ void __launch_bounds__(320) agg_kernel() {
    int h  = blockIdx.x;                       // 0..79
    int tx = threadIdx.x;                      // 0..19 -> pixels 4tx..4tx+3
    int ty = threadIdx.y;                      // 0..15
    int pbase = blockIdx.y * 32 + ty * 2;      // 2 pairs per thread

    __shared__ __align__(16) float saff[K2][W_];
    __shared__ __align__(16) float sinv[W_];
    int tid = ty * 20 + tx;
    const float* affrow = g_aff + h * W_;
    for (int idx = tid; idx < K2 * W_; idx += 320) {
        int k2 = idx / W_;
        int ww = idx - k2 * W_;
        saff[k2][ww] = affrow[k2 * HW + ww];
    }
    __syncthreads();
    if (tid < W_) {
        float s = 0.0f;
#pragma unroll
        for (int k = 0; k < K2; k++) s += saff[k][tid];
        sinv[tid] = 1.0f / s;
    }
    __syncthreads();

    float2 acc[4][2];   // [px][pair]: x = low channel, y = high channel
#pragma unroll
    for (int px = 0; px < 4; px++)
#pragma unroll
        for (int pr = 0; pr < 2; pr++) acc[px][pr] = make_float2(0.f, 0.f);

    const uint4 z4 = make_uint4(0u, 0u, 0u, 0u);
    bool haveA = (tx > 0), haveC = (tx < 19);

    for (int i = 0; i < KS; i++) {
        int hh = h + i - 3;
        if (hh < 0 || hh >= H_) continue;

        float4 s[KS];
#pragma unroll
        for (int j = 0; j < KS; j++)
            s[j] = *(const float4*)&saff[i * KS + j][tx * 4];

#pragma unroll
        for (int pr = 0; pr < 2; pr++) {
            const unsigned* mrow = g_msgpk + (pbase + pr) * HW + hh * W_;
            uint4 va = haveA ? *(const uint4*)(mrow + tx * 4 - 4) : z4;
            uint4 vb = *(const uint4*)(mrow + tx * 4);
            uint4 vc = haveC ? *(const uint4*)(mrow + tx * 4 + 4) : z4;
            unsigned wd[10] = {va.y, va.z, va.w,
                               vb.x, vb.y, vb.z, vb.w,
                               vc.x, vc.y, vc.z};
            float wl[10], wh[10];
#pragma unroll
            for (int q = 0; q < 10; q++) {
                wl[q] = __uint_as_float(wd[q] << 16);
                wh[q] = __uint_as_float(wd[q] & 0xFFFF0000u);
            }
#pragma unroll
            for (int j = 0; j < KS; j++) {
                acc[0][pr].x += wl[j + 0] * s[j].x;
                acc[0][pr].y += wh[j + 0] * s[j].x;
                acc[1][pr].x += wl[j + 1] * s[j].y;
                acc[1][pr].y += wh[j + 1] * s[j].y;
                acc[2][pr].x += wl[j + 2] * s[j].z;
                acc[2][pr].y += wh[j + 2] * s[j].z;
                acc[3][pr].x += wl[j + 3] * s[j].w;
                acc[3][pr].y += wh[j + 3] * s[j].w;
            }
        }
    }

    float4 si = *(const float4*)&sinv[tx * 4];
#pragma unroll
    for (int pr = 0; pr < 2; pr++) {
        int pid = pbase + pr;
        int c0 = (pid >> 3) * 16 + (pid & 7);
        int c1 = c0 + 8;
        float4 lo = make_float4(acc[0][pr].x * si.x, acc[1][pr].x * si.y,
                                acc[2][pr].x * si.z, acc[3][pr].x * si.w);
        float4 hi = make_float4(acc[0][pr].y * si.x, acc[1][pr].y * si.y,
                                acc[2][pr].y * si.z, acc[3][pr].y * si.w);
        *(float4*)(g_agg + c0 * HW + h * W_ + tx * 4) = lo;
        *(float4*)(g_agg + c1 * HW + h * W_ + tx * 4) = hi;
    }
}

// ---------------------------------------------------------------------------
// Launch
// ---------------------------------------------------------------------------
extern "C" void kernel_launch(void* const* d_in, const int* in_sizes, int n_in,
                              void* d_out, int out_size) {
    const float* x      = (const float*)d_in[0];
    const float* coarse = (const float*)d_in[1];
    const float* sigma  = (const float*)d_in[2];
    const float* wfeat  = (const float*)d_in[3];
    const float* wfuse  = (const float*)d_in[4];
    const float* gamma  = (const float*)d_in[5];
    const float* beta   = (const float*)d_in[6];
    const float* mean   = (const float*)d_in[7];
    const float* var    = (const float*)d_in[8];
    float* out = (float*)d_out;

    float *wa1, *wa2, *bias, *agg;
    unsigned* msgpk;
    cudaGetSymbolAddress((void**)&wa1,   g_wa1);
    cudaGetSymbolAddress((void**)&wa2,   g_wa2);
    cudaGetSymbolAddress((void**)&bias,  g_bias);
    cudaGetSymbolAddress((void**)&msgpk, g_msgpk);
    cudaGetSymbolAddress((void**)&agg,   g_agg);

    // weight rearrange + bias
    setup_kernel<<<1280, 160>>>(wfeat, wfuse, gamma, beta, mean, var);
    // GEMM1 (messages, packed bf16x2) fused with independent affinity taps
    fused_g1_aff_kernel<<<498, 256>>>(coarse, sigma, wa1, x, msgpk, bias);
    // spatially-varying 7x7 aggregation with fused softmax normalization
    agg_kernel<<<dim3(H_, C_ / 64), dim3(20, 16)>>>();
    // out = x + w_fuse @ agg
    gemm2_kernel<<<dim3(HW / GBN, C_ / GBM), 256>>>(wa2, agg, out, x);
}

// round 15
// speedup vs baseline: 1.9755x; 1.0913x over previous
#include <cuda_runtime.h>
#include <cuda_bf16.h>
#include <math.h>

#define H_  80
#define W_  80
#define HW  6400
#define C_  256
#define CP  19
#define KS  7
#define K2  49

// Scratch (allocation-free: __device__ globals)
__device__ float g_bias[C_];           // BN-folded bias for w_feat
__device__ float g_wa1[C_ * C_];       // fragment-ordered BN-folded w_feat
__device__ float g_wa2[C_ * C_];       // fragment-ordered w_fuse
__device__ unsigned g_msgpk[128 * HW]; // messages, bf16x2 pairs (c, c+8)
__device__ unsigned g_aggpk[128 * HW]; // aggregated, bf16x2 pairs (k, k+4)
__device__ float g_aff[K2 * HW];       // unnormalized affinity exp(exp(-d/denom))

// ---------------------------------------------------------------------------
// Front kernel (R9-proven): blockIdx-partitioned union of
//   [0,140)      affinity taps   [140,1164) weight rearrange
//   [1164,1420)  BN-folded bias reduction
// Fragment order: [kb 0..31][mb 0..15][lane][a0..a3].
// ---------------------------------------------------------------------------
__global__ void __launch_bounds__(160) front_kernel(
        const float* __restrict__ coarse, const float* __restrict__ sigma,
        const float* __restrict__ wfeat,  const float* __restrict__ wfuse,
        const float* __restrict__ gamma,  const float* __restrict__ beta,
        const float* __restrict__ mean,   const float* __restrict__ var) {
    int b = blockIdx.x;
    int t = threadIdx.x;

    if (b < 140) {
        int tx = t % 40;                  // pixels 2tx, 2tx+1
        int h  = (b % 20) * 4 + t / 40;
        int i  = b / 20;                  // tap row 0..6
        int b0 = tx * 2;

        float sr = fmaxf(sigma[0], 0.0f);
        float invd = 1.0f / (2.0f * sr * sr + 1e-8f);

        int hh = h + i - 3;
        bool rowok = (hh >= 0) && (hh < H_);
        const float* crow = coarse + h * W_;
        const float* nrow = coarse + (rowok ? hh : 0) * W_;

        bool v[5];
#pragma unroll
        for (int l = 0; l < 5; l++) {
            int col = b0 - 4 + 2 * l;
            v[l] = rowok && (col >= 0) && (col <= W_ - 2);
        }

        float d[KS][2];
#pragma unroll
        for (int j = 0; j < KS; j++) { d[j][0] = 0.0f; d[j][1] = 0.0f; }

        const float2 z2 = make_float2(0.0f, 0.0f);
#pragma unroll
        for (int cp = 0; cp < CP; cp++) {
            float2 cen = *(const float2*)(crow + cp * HW + b0);
            const float* nb = nrow + cp * HW;
            float win[8];
            float2 L;
            L = v[0] ? *(const float2*)(nb + b0 - 4) : z2; win[0] = L.y;
            L = v[1] ? *(const float2*)(nb + b0 - 2) : z2; win[1] = L.x; win[2] = L.y;
            L = v[2] ? *(const float2*)(nb + b0)     : z2; win[3] = L.x; win[4] = L.y;
            L = v[3] ? *(const float2*)(nb + b0 + 2) : z2; win[5] = L.x; win[6] = L.y;
            L = v[4] ? *(const float2*)(nb + b0 + 4) : z2; win[7] = L.x;
#pragma unroll
            for (int j = 0; j < KS; j++) {
                float t0 = win[j]     - cen.x; d[j][0] += t0 * t0;
                float t1 = win[j + 1] - cen.y; d[j][1] += t1 * t1;
            }
        }

        int p = h * W_ + b0;
#pragma unroll
        for (int j = 0; j < KS; j++) {
            g_aff[(i * KS + j) * HW + p]     = __expf(__expf(-d[j][0] * invd));
            g_aff[(i * KS + j) * HW + p + 1] = __expf(__expf(-d[j][1] * invd));
        }
    } else if (b < 1164) {
        if (t < 128) {
            int bb = b - 140;
            int w2 = bb >> 9;             // 0: wfeat (scaled), 1: wfuse
            bb &= 511;
            int kb = bb & 31, mb = bb >> 5;
            int lane = t & 31, q = t >> 5;
            int gid = lane >> 2, tig = lane & 3;
            int row = mb * 16 + gid + (q & 1) * 8;
            int col = kb * 8 + tig + (q >> 1) * 4;
            const float* src = w2 ? wfuse : wfeat;
            float v = src[row * C_ + col];
            if (!w2) v *= gamma[col] * rsqrtf(var[col] + 1e-5f);
            float* dst = w2 ? g_wa2 : g_wa1;
            dst[((kb * 16 + mb) * 32 + lane) * 4 + q] = v;
        }
    } else {
        int o = b - 1164;                 // 0..255
        float s = 0.0f;
        for (int c = t; c < C_; c += 160) {
            float a = gamma[c] * rsqrtf(var[c] + 1e-5f);
            s += wfeat[o * C_ + c] * (beta[c] - mean[c] * a);
        }
#pragma unroll
        for (int off = 16; off; off >>= 1) s += __shfl_xor_sync(~0u, s, off);
        __shared__ float red[5];
        if ((t & 31) == 0) red[t >> 5] = s;
        __syncthreads();
        if (t == 0) g_bias[o] = red[0] + red[1] + red[2] + red[3] + red[4];
    }
}

// ---------------------------------------------------------------------------
// Common MMA helpers
// ---------------------------------------------------------------------------
#define GBM 64
#define GBN 64
#define GBK 32
#define BSTR (GBN + 8)
#define NSTG 3

__device__ __forceinline__ void cp16(void* smem, const void* gmem) {
    unsigned s = (unsigned)__cvta_generic_to_shared(smem);
    asm volatile("cp.async.ca.shared.global [%0], [%1], 16;\n" :: "r"(s), "l"(gmem));
}

__device__ __forceinline__ void mma_tf32(float* c, const unsigned* a, const unsigned* b) {
    asm volatile(
        "mma.sync.aligned.m16n8k8.row.col.f32.tf32.tf32.f32 "
        "{%0,%1,%2,%3}, {%4,%5,%6,%7}, {%8,%9}, {%0,%1,%2,%3};\n"
        : "+f"(c[0]), "+f"(c[1]), "+f"(c[2]), "+f"(c[3])
        : "r"(a[0]), "r"(a[1]), "r"(a[2]), "r"(a[3]), "r"(b[0]), "r"(b[1]));
}

// ---------------------------------------------------------------------------
// GEMM1 (R8-proven): fp32 B via 3-stage cp.async, A-frags via LDG.
// Emits bf16x2 channel-pairs (rows r, r+8) to g_msgpk. Grid 100x4.
// ---------------------------------------------------------------------------
__global__ void __launch_bounds__(256) gemm1_kernel(
        const float* __restrict__ Afrag,
        const float* __restrict__ B,
        unsigned* __restrict__ msgpk,
        const float* __restrict__ bias) {
    __shared__ __align__(16) float Bs[NSTG][GBK][BSTR];
    const int N = HW;

    int t    = threadIdx.x;
    int warp = t >> 5, lane = t & 31;
    int gid  = lane >> 2, tig = lane & 3;
    int wm   = warp >> 2, wn = warp & 3;
    int m0   = blockIdx.y * GBM, n0 = blockIdx.x * GBN;
    int mb0  = blockIdx.y * 4 + wm * 2;

    int kr0 = t >> 4;
    int co  = (t & 15) * 4;

    float acc[2][2][4];
#pragma unroll
    for (int mi = 0; mi < 2; mi++)
#pragma unroll
        for (int ni = 0; ni < 2; ni++)
#pragma unroll
            for (int q = 0; q < 4; q++) acc[mi][ni][q] = 0.0f;

#define LOADB(s, k0)                                                          \
    {                                                                          \
        cp16(&Bs[s][kr0][co],      B + ((k0) + kr0) * N + n0 + co);            \
        cp16(&Bs[s][kr0 + 16][co], B + ((k0) + kr0 + 16) * N + n0 + co);       \
        asm volatile("cp.async.commit_group;\n");                              \
    }

    LOADB(0, 0);
    LOADB(1, GBK);

    const int NIT = C_ / GBK;   // 8
    for (int it = 0; it < NIT; it++) {
        if (it + 1 < NIT) asm volatile("cp.async.wait_group 1;\n");
        else              asm volatile("cp.async.wait_group 0;\n");
        __syncthreads();
        if (it + 2 < NIT) LOADB((it + 2) % NSTG, (it + 2) * GBK);

        int s = it % NSTG;
#pragma unroll
        for (int kk = 0; kk < GBK / 8; kk++) {
            int kbg = it * 4 + kk;
            float4 a0 = *(const float4*)(Afrag + ((kbg * 16 + mb0) * 32 + lane) * 4);
            float4 a1 = *(const float4*)(Afrag + ((kbg * 16 + mb0 + 1) * 32 + lane) * 4);
            unsigned aR[2][4];
            aR[0][0] = __float_as_uint(a0.x); aR[0][1] = __float_as_uint(a0.y);
            aR[0][2] = __float_as_uint(a0.z); aR[0][3] = __float_as_uint(a0.w);
            aR[1][0] = __float_as_uint(a1.x); aR[1][1] = __float_as_uint(a1.y);
            aR[1][2] = __float_as_uint(a1.z); aR[1][3] = __float_as_uint(a1.w);

            unsigned bR[2][2];
#pragma unroll
            for (int ni = 0; ni < 2; ni++) {
                int cN = wn * 16 + ni * 8 + gid;
                bR[ni][0] = __float_as_uint(Bs[s][kk * 8 + tig][cN]);
                bR[ni][1] = __float_as_uint(Bs[s][kk * 8 + tig + 4][cN]);
            }
#pragma unroll
            for (int mi = 0; mi < 2; mi++)
#pragma unroll
                for (int ni = 0; ni < 2; ni++)
                    mma_tf32(acc[mi][ni], aR[mi], bR[ni]);
        }
        __syncthreads();
    }

#pragma unroll
    for (int mi = 0; mi < 2; mi++) {
        int r0 = m0 + wm * 32 + mi * 16 + gid;
        float b0v = bias[r0];
        float b1v = bias[r0 + 8];
        int pid = ((m0 >> 4) + wm * 2 + mi) * 8 + gid;
#pragma unroll
        for (int ni = 0; ni < 2; ni++) {
            int col = n0 + wn * 16 + ni * 8 + tig * 2;
            __nv_bfloat162 w0 = __floats2bfloat162_rn(acc[mi][ni][0] + b0v,
                                                      acc[mi][ni][2] + b1v);
            __nv_bfloat162 w1 = __floats2bfloat162_rn(acc[mi][ni][1] + b0v,
                                                      acc[mi][ni][3] + b1v);
            uint2 pk;
            pk.x = *reinterpret_cast<unsigned*>(&w0);
            pk.y = *reinterpret_cast<unsigned*>(&w1);
            *(uint2*)(msgpk + pid * N + col) = pk;
        }
    }
#undef LOADB
}

// ---------------------------------------------------------------------------
// GEMM2: B is the bf16x2-PACKED agg (rows pack channels k and k+4 — exactly
// the m16n8k8 B-frag pairing). One LDS.32 + 2 logic ops per frag (was 2 LDS).
// Smem/stage 4KB; stride 72 keeps 8*tig+gid bank-free. fp32 + resid epilogue.
// ---------------------------------------------------------------------------
#define BSTR2 72

__global__ void __launch_bounds__(256) gemm2_kernel(
        const float* __restrict__ Afrag,
        const unsigned* __restrict__ Bpk,   // [128][HW] packed (k, k+4)
        float* __restrict__ Cout,
        const float* __restrict__ resid) {
    __shared__ __align__(16) unsigned Bs2[NSTG][16][BSTR2];
    const int N = HW;

    int t    = threadIdx.x;
    int warp = t >> 5, lane = t & 31;
    int gid  = lane >> 2, tig = lane & 3;
    int wm   = warp >> 2, wn = warp & 3;
    int m0   = blockIdx.y * GBM, n0 = blockIdx.x * GBN;
    int mb0  = blockIdx.y * 4 + wm * 2;

    int prow = t >> 4;             // 0..15 packed rows per stage
    int pco  = (t & 15) * 4;       // word offset

    float acc[2][2][4];
#pragma unroll
    for (int mi = 0; mi < 2; mi++)
#pragma unroll
        for (int ni = 0; ni < 2; ni++)
#pragma unroll
            for (int q = 0; q < 4; q++) acc[mi][ni][q] = 0.0f;

#define LOADB2(s, k0)                                                         \
    {                                                                          \
        cp16(&Bs2[s][prow][pco], Bpk + (((k0) >> 1) + prow) * N + n0 + pco);   \
        asm volatile("cp.async.commit_group;\n");                              \
    }

    LOADB2(0, 0);
    LOADB2(1, GBK);

    const int NIT = C_ / GBK;   // 8
    for (int it = 0; it < NIT; it++) {
        if (it + 1 < NIT) asm volatile("cp.async.wait_group 1;\n");
        else              asm volatile("cp.async.wait_group 0;\n");
        __syncthreads();
        if (it + 2 < NIT) LOADB2((it + 2) % NSTG, (it + 2) * GBK);

        int s = it % NSTG;
#pragma unroll
        for (int kk = 0; kk < GBK / 8; kk++) {
            int kbg = it * 4 + kk;
            float4 a0 = *(const float4*)(Afrag + ((kbg * 16 + mb0) * 32 + lane) * 4);
            float4 a1 = *(const float4*)(Afrag + ((kbg * 16 + mb0 + 1) * 32 + lane) * 4);
            unsigned aR[2][4];
            aR[0][0] = __float_as_uint(a0.x); aR[0][1] = __float_as_uint(a0.y);
            aR[0][2] = __float_as_uint(a0.z); aR[0][3] = __float_as_uint(a0.w);
            aR[1][0] = __float_as_uint(a1.x); aR[1][1] = __float_as_uint(a1.y);
            aR[1][2] = __float_as_uint(a1.z); aR[1][3] = __float_as_uint(a1.w);

            unsigned bR[2][2];
#pragma unroll
            for (int ni = 0; ni < 2; ni++) {
                int cN = wn * 16 + ni * 8 + gid;
                unsigned wd = Bs2[s][kk * 4 + tig][cN];
                bR[ni][0] = wd << 16;            // channel k (bf16 -> fp32 exact)
                bR[ni][1] = wd & 0xFFFF0000u;    // channel k+4
            }
#pragma unroll
            for (int mi = 0; mi < 2; mi++)
#pragma unroll
                for (int ni = 0; ni < 2; ni++)
                    mma_tf32(acc[mi][ni], aR[mi], bR[ni]);
        }
        __syncthreads();
    }

#pragma unroll
    for (int mi = 0; mi < 2; mi++) {
        int r0 = m0 + wm * 32 + mi * 16 + gid;
        int r1 = r0 + 8;
#pragma unroll
        for (int ni = 0; ni < 2; ni++) {
            int col = n0 + wn * 16 + ni * 8 + tig * 2;
            float2 v0, v1;
            float2 rv0 = *(const float2*)(resid + r0 * N + col);
            float2 rv1 = *(const float2*)(resid + r1 * N + col);
            v0.x = acc[mi][ni][0] + rv0.x;
            v0.y = acc[mi][ni][1] + rv0.y;
            v1.x = acc[mi][ni][2] + rv1.x;
            v1.y = acc[mi][ni][3] + rv1.y;
            *(float2*)(Cout + r0 * N + col) = v0;
            *(float2*)(Cout + r1 * N + col) = v1;
        }
    }
#undef LOADB2
}

// ---------------------------------------------------------------------------
// Aggregation: 4 pixels x 2 pids per thread; pid pair {p0, p0+4} so each
// thread holds channels (c, c+4, c+8, c+12) and can emit the (k, k+4)
// packed words gemm2 needs. Block (20,16)=320 thr, grid (80,4).
// ---------------------------------------------------------------------------
__global__ void __launch_bounds__(320) agg_kernel() {
    int h  = blockIdx.x;                       // 0..79
    int tx = threadIdx.x;                      // 0..19 -> pixels 4tx..4tx+3
    int ty = threadIdx.y;                      // 0..15
    int B16 = blockIdx.y * 4 + (ty >> 2);      // 16-channel block
    int g   = ty & 3;
    int p0  = B16 * 8 + g;                     // pids p0, p0+4

    __shared__ __align__(16) float saff[K2][W_];
    __shared__ __align__(16) float sinv[W_];
    int tid = ty * 20 + tx;
    const float* affrow = g_aff + h * W_;
    for (int idx = tid; idx < K2 * W_; idx += 320) {
        int k2 = idx / W_;
        int ww = idx - k2 * W_;
        saff[k2][ww] = affrow[k2 * HW + ww];
    }
    __syncthreads();
    if (tid < W_) {
        float s = 0.0f;
#pragma unroll
        for (int k = 0; k < K2; k++) s += saff[k][tid];
        sinv[tid] = 1.0f / s;
    }
    __syncthreads();

    float2 acc[4][2];   // [px][pr]: pr 0 -> pid p0, pr 1 -> pid p0+4
#pragma unroll
    for (int px = 0; px < 4; px++)
#pragma unroll
        for (int pr = 0; pr < 2; pr++) acc[px][pr] = make_float2(0.f, 0.f);

    const uint4 z4 = make_uint4(0u, 0u, 0u, 0u);
    bool haveA = (tx > 0), haveC = (tx < 19);

    for (int i = 0; i < KS; i++) {
        int hh = h + i - 3;
        if (hh < 0 || hh >= H_) continue;

        float4 s[KS];
#pragma unroll
        for (int j = 0; j < KS; j++)
            s[j] = *(const float4*)&saff[i * KS + j][tx * 4];

#pragma unroll
        for (int pr = 0; pr < 2; pr++) {
            const unsigned* mrow = g_msgpk + (p0 + pr * 4) * HW + hh * W_;
            uint4 va = haveA ? *(const uint4*)(mrow + tx * 4 - 4) : z4;
            uint4 vb = *(const uint4*)(mrow + tx * 4);
            uint4 vc = haveC ? *(const uint4*)(mrow + tx * 4 + 4) : z4;
            unsigned wd[10] = {va.y, va.z, va.w,
                               vb.x, vb.y, vb.z, vb.w,
                               vc.x, vc.y, vc.z};
            float wl[10], wh[10];
#pragma unroll
            for (int q = 0; q < 10; q++) {
                wl[q] = __uint_as_float(wd[q] << 16);
                wh[q] = __uint_as_float(wd[q] & 0xFFFF0000u);
            }
#pragma unroll
            for (int j = 0; j < KS; j++) {
                acc[0][pr].x += wl[j + 0] * s[j].x;
                acc[0][pr].y += wh[j + 0] * s[j].x;
                acc[1][pr].x += wl[j + 1] * s[j].y;
                acc[1][pr].y += wh[j + 1] * s[j].y;
                acc[2][pr].x += wl[j + 2] * s[j].z;
                acc[2][pr].y += wh[j + 2] * s[j].z;
                acc[3][pr].x += wl[j + 3] * s[j].w;
                acc[3][pr].y += wh[j + 3] * s[j].w;
            }
        }
    }

    float4 si = *(const float4*)&sinv[tx * 4];
    float sv[4] = {si.x, si.y, si.z, si.w};
    // Packed rows: r0 = 8*B16+g holds (c0, c0+4); r0+4 holds (c0+8, c0+12)
    int r0 = B16 * 8 + g;
    uint4 w0, w1;
    unsigned* w0p = &w0.x;
    unsigned* w1p = &w1.x;
#pragma unroll
    for (int px = 0; px < 4; px++) {
        __nv_bfloat162 lo = __floats2bfloat162_rn(acc[px][0].x * sv[px],
                                                  acc[px][1].x * sv[px]);
        __nv_bfloat162 hi = __floats2bfloat162_rn(acc[px][0].y * sv[px],
                                                  acc[px][1].y * sv[px]);
        w0p[px] = *reinterpret_cast<unsigned*>(&lo);
        w1p[px] = *reinterpret_cast<unsigned*>(&hi);
    }
    *(uint4*)(g_aggpk + r0 * HW + h * W_ + tx * 4)       = w0;
    *(uint4*)(g_aggpk + (r0 + 4) * HW + h * W_ + tx * 4) = w1;
}

// ---------------------------------------------------------------------------
// Launch
// ---------------------------------------------------------------------------
extern "C" void kernel_launch(void* const* d_in, const int* in_sizes, int n_in,
                              void* d_out, int out_size) {
    const float* x      = (const float*)d_in[0];
    const float* coarse = (const float*)d_in[1];
    const float* sigma  = (const float*)d_in[2];
    const float* wfeat  = (const float*)d_in[3];
    const float* wfuse  = (const float*)d_in[4];
    const float* gamma  = (const float*)d_in[5];
    const float* beta   = (const float*)d_in[6];
    const float* mean   = (const float*)d_in[7];
    const float* var    = (const float*)d_in[8];
    float* out = (float*)d_out;

    float *wa1, *wa2, *bias;
    unsigned *msgpk, *aggpk;
    cudaGetSymbolAddress((void**)&wa1,   g_wa1);
    cudaGetSymbolAddress((void**)&wa2,   g_wa2);
    cudaGetSymbolAddress((void**)&bias,  g_bias);
    cudaGetSymbolAddress((void**)&msgpk, g_msgpk);
    cudaGetSymbolAddress((void**)&aggpk, g_aggpk);

    // affinity taps + weight rearrange + bias, one launch
    front_kernel<<<1420, 160>>>(coarse, sigma, wfeat, wfuse,
                                gamma, beta, mean, var);
    // messages = w' @ x + bias  (packed bf16x2 channel-pair output)
    gemm1_kernel<<<dim3(HW / GBN, C_ / GBM), 256>>>(wa1, x, msgpk, bias);
    // spatially-varying 7x7 aggregation -> packed (k, k+4) bf16x2
    agg_kernel<<<dim3(H_, C_ / 64), dim3(20, 16)>>>();
    // out = x + w_fuse @ agg   (B from packed buffer)
    gemm2_kernel<<<dim3(HW / GBN, C_ / GBM), 256>>>(wa2, aggpk, out, x);
}

// round 16
// speedup vs baseline: 2.2074x; 1.1174x over previous
#include <cuda_runtime.h>
#include <cuda_bf16.h>
#include <math.h>

#define H_  80
#define W_  80
#define HW  6400
#define C_  256
#define CP  19
#define KS  7
#define K2  49

// Scratch (allocation-free: __device__ globals)
__device__ float    g_bias[C_];          // BN-folded bias for w_feat
__device__ unsigned g_wa1pk[16*16*32*4]; // bf16x2 fragment-ordered BN-folded w_feat
__device__ unsigned g_wa2pk[16*16*32*4]; // bf16x2 fragment-ordered w_fuse
__device__ unsigned g_xpk[128 * HW];     // x packed bf16x2 (channels 2k, 2k+1)
__device__ unsigned g_msgpk[128 * HW];   // messages bf16x2 pairs (c, c+8)
__device__ unsigned g_aggpk[128 * HW];   // agg bf16x2 adjacent pairs (2k, 2k+1)
__device__ float    g_aff[K2 * HW];      // unnormalized affinity

// ---------------------------------------------------------------------------
// Front kernel: blockIdx-partitioned union of
//   [0,140)     affinity taps
//   [140,652)   weight rearrange -> bf16x2 m16n8k16 A-fragments
//   [652,908)   x packing -> bf16x2 adjacent-channel pairs
//   [908,1164)  BN-folded bias reduction
// A-frag (16x16): q0=(gid,2tig:2tig+1) q1=(gid+8,..) q2=(gid,2tig+8:+9) q3=(gid+8,..)
// ---------------------------------------------------------------------------
__global__ void __launch_bounds__(160) front_kernel(
        const float* __restrict__ x,
        const float* __restrict__ coarse, const float* __restrict__ sigma,
        const float* __restrict__ wfeat,  const float* __restrict__ wfuse,
        const float* __restrict__ gamma,  const float* __restrict__ beta,
        const float* __restrict__ mean,   const float* __restrict__ var) {
    int b = blockIdx.x;
    int t = threadIdx.x;

    if (b < 140) {
        // ---- affinity: 2 pixels per thread, sliding window ----
        int tx = t % 40;                  // pixels 2tx, 2tx+1
        int h  = (b % 20) * 4 + t / 40;
        int i  = b / 20;                  // tap row 0..6
        int b0 = tx * 2;

        float sr = fmaxf(sigma[0], 0.0f);
        float invd = 1.0f / (2.0f * sr * sr + 1e-8f);

        int hh = h + i - 3;
        bool rowok = (hh >= 0) && (hh < H_);
        const float* crow = coarse + h * W_;
        const float* nrow = coarse + (rowok ? hh : 0) * W_;

        bool v[5];
#pragma unroll
        for (int l = 0; l < 5; l++) {
            int col = b0 - 4 + 2 * l;
            v[l] = rowok && (col >= 0) && (col <= W_ - 2);
        }

        float d[KS][2];
#pragma unroll
        for (int j = 0; j < KS; j++) { d[j][0] = 0.0f; d[j][1] = 0.0f; }

        const float2 z2 = make_float2(0.0f, 0.0f);
#pragma unroll
        for (int cp = 0; cp < CP; cp++) {
            float2 cen = *(const float2*)(crow + cp * HW + b0);
            const float* nb = nrow + cp * HW;
            float win[8];
            float2 L;
            L = v[0] ? *(const float2*)(nb + b0 - 4) : z2; win[0] = L.y;
            L = v[1] ? *(const float2*)(nb + b0 - 2) : z2; win[1] = L.x; win[2] = L.y;
            L = v[2] ? *(const float2*)(nb + b0)     : z2; win[3] = L.x; win[4] = L.y;
            L = v[3] ? *(const float2*)(nb + b0 + 2) : z2; win[5] = L.x; win[6] = L.y;
            L = v[4] ? *(const float2*)(nb + b0 + 4) : z2; win[7] = L.x;
#pragma unroll
            for (int j = 0; j < KS; j++) {
                float t0 = win[j]     - cen.x; d[j][0] += t0 * t0;
                float t1 = win[j + 1] - cen.y; d[j][1] += t1 * t1;
            }
        }

        int p = h * W_ + b0;
#pragma unroll
        for (int j = 0; j < KS; j++) {
            g_aff[(i * KS + j) * HW + p]     = __expf(__expf(-d[j][0] * invd));
            g_aff[(i * KS + j) * HW + p + 1] = __expf(__expf(-d[j][1] * invd));
        }
    } else if (b < 652) {
        // ---- weight rearrange -> bf16 fragments ----
        if (t < 128) {
            int bb = b - 140;
            int w2 = bb >> 8;             // 0: wfeat (scaled), 1: wfuse
            bb &= 255;
            int kb16 = bb & 15, mb = bb >> 4;
            int lane = t & 31, q = t >> 5;
            int gid = lane >> 2, tig = lane & 3;
            int row = mb * 16 + gid + (q & 1) * 8;
            int k0  = kb16 * 16 + tig * 2 + (q >> 1) * 8;
            const float* src = w2 ? wfuse : wfeat;
            float v0 = src[row * C_ + k0];
            float v1 = src[row * C_ + k0 + 1];
            if (!w2) {
                v0 *= gamma[k0]     * rsqrtf(var[k0]     + 1e-5f);
                v1 *= gamma[k0 + 1] * rsqrtf(var[k0 + 1] + 1e-5f);
            }
            __nv_bfloat162 w = __floats2bfloat162_rn(v0, v1);
            unsigned* dst = w2 ? g_wa2pk : g_wa1pk;
            dst[((kb16 * 16 + mb) * 32 + lane) * 4 + q] =
                *reinterpret_cast<unsigned*>(&w);
        }
    } else if (b < 908) {
        // ---- x packing: row kp holds bf16x2 (x[2kp], x[2kp+1]) ----
        int b2 = b - 652;                 // 0..255
        int kp = b2 >> 1;
        int base = (b2 & 1) * 3200;
        const float* x0 = x + (2 * kp) * HW;
        const float* x1 = x + (2 * kp + 1) * HW;
        unsigned* dst = g_xpk + kp * HW;
        for (int idx = t; idx < 3200; idx += 160) {
            int p = base + idx;
            __nv_bfloat162 w = __floats2bfloat162_rn(x0[p], x1[p]);
            dst[p] = *reinterpret_cast<unsigned*>(&w);
        }
    } else {
        // ---- bias reduction ----
        int o = b - 908;                  // 0..255
        float s = 0.0f;
        for (int c = t; c < C_; c += 160) {
            float a = gamma[c] * rsqrtf(var[c] + 1e-5f);
            s += wfeat[o * C_ + c] * (beta[c] - mean[c] * a);
        }
#pragma unroll
        for (int off = 16; off; off >>= 1) s += __shfl_xor_sync(~0u, s, off);
        __shared__ float red[5];
        if ((t & 31) == 0) red[t >> 5] = s;
        __syncthreads();
        if (t == 0) g_bias[o] = red[0] + red[1] + red[2] + red[3] + red[4];
    }
}

// ---------------------------------------------------------------------------
// bf16 m16n8k16 GEMM body. A-frags: one LDG.128 per (k16, mi). B: packed
// bf16x2 rows via 3-stage cp.async (4KB/stage, stride 72 bank-free).
// Tile 64x64, BK=32, 8 warps (2x4), warp 32x16.
// ---------------------------------------------------------------------------
#define GBM 64
#define GBN 64
#define GBK 32
#define BSTR2 72
#define NSTG 3

__device__ __forceinline__ void cp16(void* smem, const void* gmem) {
    unsigned s = (unsigned)__cvta_generic_to_shared(smem);
    asm volatile("cp.async.ca.shared.global [%0], [%1], 16;\n" :: "r"(s), "l"(gmem));
}

__device__ __forceinline__ void mma_bf16(float* c, const unsigned* a, const unsigned* b) {
    asm volatile(
        "mma.sync.aligned.m16n8k16.row.col.f32.bf16.bf16.f32 "
        "{%0,%1,%2,%3}, {%4,%5,%6,%7}, {%8,%9}, {%0,%1,%2,%3};\n"
        : "+f"(c[0]), "+f"(c[1]), "+f"(c[2]), "+f"(c[3])
        : "r"(a[0]), "r"(a[1]), "r"(a[2]), "r"(a[3]), "r"(b[0]), "r"(b[1]));
}

__device__ __forceinline__ void gemm_body_bf16(
        int bx, int by,
        const unsigned* __restrict__ Afrag,   // [16][16][32][4] bf16x2 words
        const unsigned* __restrict__ Bpk,     // [128][HW] packed (2k, 2k+1)
        float* __restrict__ Cout,
        unsigned* __restrict__ msgpk,
        const float* __restrict__ bias,
        const float* __restrict__ resid) {
    __shared__ __align__(16) unsigned Bs[NSTG][16][BSTR2];
    const int N = HW;

    int t    = threadIdx.x;
    int warp = t >> 5, lane = t & 31;
    int gid  = lane >> 2, tig = lane & 3;
    int wm   = warp >> 2, wn = warp & 3;
    int m0   = by * GBM, n0 = bx * GBN;
    int mb0  = by * 4 + wm * 2;

    int prow = t >> 4;             // 0..15 packed rows per 32-k stage
    int pco  = (t & 15) * 4;

    float acc[2][2][4];
#pragma unroll
    for (int mi = 0; mi < 2; mi++)
#pragma unroll
        for (int ni = 0; ni < 2; ni++)
#pragma unroll
            for (int q = 0; q < 4; q++) acc[mi][ni][q] = 0.0f;

#define LOADBP(s, k0)                                                         \
    {                                                                          \
        cp16(&Bs[s][prow][pco], Bpk + (((k0) >> 1) + prow) * N + n0 + pco);    \
        asm volatile("cp.async.commit_group;\n");                              \
    }

    LOADBP(0, 0);
    LOADBP(1, GBK);

    const int NIT = C_ / GBK;   // 8
    for (int it = 0; it < NIT; it++) {
        if (it + 1 < NIT) asm volatile("cp.async.wait_group 1;\n");
        else              asm volatile("cp.async.wait_group 0;\n");
        __syncthreads();
        if (it + 2 < NIT) LOADBP((it + 2) % NSTG, (it + 2) * GBK);

        int s = it % NSTG;
#pragma unroll
        for (int kk = 0; kk < 2; kk++) {          // two k16 blocks per iter
            int kbg16 = it * 2 + kk;
            uint4 a0 = *(const uint4*)(Afrag + ((kbg16 * 16 + mb0) * 32 + lane) * 4);
            uint4 a1 = *(const uint4*)(Afrag + ((kbg16 * 16 + mb0 + 1) * 32 + lane) * 4);
            unsigned aR[2][4] = {{a0.x, a0.y, a0.z, a0.w},
                                 {a1.x, a1.y, a1.z, a1.w}};
            unsigned bR[2][2];
#pragma unroll
            for (int ni = 0; ni < 2; ni++) {
                int cN = wn * 16 + ni * 8 + gid;
                bR[ni][0] = Bs[s][kk * 8 + tig][cN];      // (k=2tig, 2tig+1)
                bR[ni][1] = Bs[s][kk * 8 + tig + 4][cN];  // (k=2tig+8, +9)
            }
#pragma unroll
            for (int mi = 0; mi < 2; mi++)
#pragma unroll
                for (int ni = 0; ni < 2; ni++)
                    mma_bf16(acc[mi][ni], aR[mi], bR[ni]);
        }
        __syncthreads();
    }

#pragma unroll
    for (int mi = 0; mi < 2; mi++) {
        int r0 = m0 + wm * 32 + mi * 16 + gid;
        int r1 = r0 + 8;
#pragma unroll
        for (int ni = 0; ni < 2; ni++) {
            int col = n0 + wn * 16 + ni * 8 + tig * 2;
            if (msgpk) {
                float b0v = bias[r0];
                float b1v = bias[r1];
                int pid = (mb0 + mi) * 8 + gid;
                __nv_bfloat162 w0 = __floats2bfloat162_rn(acc[mi][ni][0] + b0v,
                                                          acc[mi][ni][2] + b1v);
                __nv_bfloat162 w1 = __floats2bfloat162_rn(acc[mi][ni][1] + b0v,
                                                          acc[mi][ni][3] + b1v);
                uint2 pk;
                pk.x = *reinterpret_cast<unsigned*>(&w0);
                pk.y = *reinterpret_cast<unsigned*>(&w1);
                *(uint2*)(msgpk + pid * N + col) = pk;
            } else {
                float2 rv0 = *(const float2*)(resid + r0 * N + col);
                float2 rv1 = *(const float2*)(resid + r1 * N + col);
                float2 v0, v1;
                v0.x = acc[mi][ni][0] + rv0.x;
                v0.y = acc[mi][ni][1] + rv0.y;
                v1.x = acc[mi][ni][2] + rv1.x;
                v1.y = acc[mi][ni][3] + rv1.y;
                *(float2*)(Cout + r0 * N + col) = v0;
                *(float2*)(Cout + r1 * N + col) = v1;
            }
        }
    }
#undef LOADBP
}

__global__ void __launch_bounds__(256) gemm1_kernel(
        const unsigned* __restrict__ Afrag, const unsigned* __restrict__ Bpk,
        unsigned* __restrict__ msgpk,       const float* __restrict__ bias) {
    gemm_body_bf16(blockIdx.x, blockIdx.y, Afrag, Bpk,
                   nullptr, msgpk, bias, nullptr);
}

__global__ void __launch_bounds__(256) gemm2_kernel(
        const unsigned* __restrict__ Afrag, const unsigned* __restrict__ Bpk,
        float* __restrict__ Cout,           const float* __restrict__ resid) {
    gemm_body_bf16(blockIdx.x, blockIdx.y, Afrag, Bpk,
                   Cout, nullptr, nullptr, resid);
}

// ---------------------------------------------------------------------------
// Aggregation: 4 pixels x 2 pids per thread, pid pair {p0, p0+1} (p0 even)
// so lo-halves give adjacent channels (c0, c0+1) and hi-halves (c0+8, c0+9)
// -> packed output rows kp hold (2kp, 2kp+1), the m16n8k16 B pairing.
// Block (20,16)=320 thr, grid (80,4).
// ---------------------------------------------------------------------------
__global__ void __launch_bounds__(320) agg_kernel() {
    int h  = blockIdx.x;                       // 0..79
    int tx = threadIdx.x;                      // 0..19 -> pixels 4tx..4tx+3
    int ty = threadIdx.y;                      // 0..15
    int B16 = blockIdx.y * 4 + (ty >> 2);      // 16-channel block
    int g   = ty & 3;
    int p0  = B16 * 8 + g * 2;                 // pids p0, p0+1

    __shared__ __align__(16) float saff[K2][W_];
    __shared__ __align__(16) float sinv[W_];
    int tid = ty * 20 + tx;
    const float* affrow = g_aff + h * W_;
    for (int idx = tid; idx < K2 * W_; idx += 320) {
        int k2 = idx / W_;
        int ww = idx - k2 * W_;
        saff[k2][ww] = affrow[k2 * HW + ww];
    }
    __syncthreads();
    if (tid < W_) {
        float s = 0.0f;
#pragma unroll
        for (int k = 0; k < K2; k++) s += saff[k][tid];
        sinv[tid] = 1.0f / s;
    }
    __syncthreads();

    float2 acc[4][2];   // [px][pr]: x = lo channel of pid, y = hi channel
#pragma unroll
    for (int px = 0; px < 4; px++)
#pragma unroll
        for (int pr = 0; pr < 2; pr++) acc[px][pr] = make_float2(0.f, 0.f);

    const uint4 z4 = make_uint4(0u, 0u, 0u, 0u);
    bool haveA = (tx > 0), haveC = (tx < 19);

    for (int i = 0; i < KS; i++) {
        int hh = h + i - 3;
        if (hh < 0 || hh >= H_) continue;

        float4 s[KS];
#pragma unroll
        for (int j = 0; j < KS; j++)
            s[j] = *(const float4*)&saff[i * KS + j][tx * 4];

#pragma unroll
        for (int pr = 0; pr < 2; pr++) {
            const unsigned* mrow = g_msgpk + (p0 + pr) * HW + hh * W_;
            uint4 va = haveA ? *(const uint4*)(mrow + tx * 4 - 4) : z4;
            uint4 vb = *(const uint4*)(mrow + tx * 4);
            uint4 vc = haveC ? *(const uint4*)(mrow + tx * 4 + 4) : z4;
            unsigned wd[10] = {va.y, va.z, va.w,
                               vb.x, vb.y, vb.z, vb.w,
                               vc.x, vc.y, vc.z};
            float wl[10], wh[10];
#pragma unroll
            for (int q = 0; q < 10; q++) {
                wl[q] = __uint_as_float(wd[q] << 16);
                wh[q] = __uint_as_float(wd[q] & 0xFFFF0000u);
            }
#pragma unroll
            for (int j = 0; j < KS; j++) {
                acc[0][pr].x += wl[j + 0] * s[j].x;
                acc[0][pr].y += wh[j + 0] * s[j].x;
                acc[1][pr].x += wl[j + 1] * s[j].y;
                acc[1][pr].y += wh[j + 1] * s[j].y;
                acc[2][pr].x += wl[j + 2] * s[j].z;
                acc[2][pr].y += wh[j + 2] * s[j].z;
                acc[3][pr].x += wl[j + 3] * s[j].w;
                acc[3][pr].y += wh[j + 3] * s[j].w;
            }
        }
    }

    float4 si = *(const float4*)&sinv[tx * 4];
    float sv[4] = {si.x, si.y, si.z, si.w};
    // Output rows: kp_lo = B16*8 + g -> (c0, c0+1); kp_hi = B16*8 + 4 + g
    int kp_lo = B16 * 8 + g;
    int kp_hi = kp_lo + 4;
    uint4 w0, w1;
    unsigned* w0p = &w0.x;
    unsigned* w1p = &w1.x;
#pragma unroll
    for (int px = 0; px < 4; px++) {
        __nv_bfloat162 lo = __floats2bfloat162_rn(acc[px][0].x * sv[px],
                                                  acc[px][1].x * sv[px]);
        __nv_bfloat162 hi = __floats2bfloat162_rn(acc[px][0].y * sv[px],
                                                  acc[px][1].y * sv[px]);
        w0p[px] = *reinterpret_cast<unsigned*>(&lo);
        w1p[px] = *reinterpret_cast<unsigned*>(&hi);
    }
    *(uint4*)(g_aggpk + kp_lo * HW + h * W_ + tx * 4) = w0;
    *(uint4*)(g_aggpk + kp_hi * HW + h * W_ + tx * 4) = w1;
}

// ---------------------------------------------------------------------------
// Launch
// ---------------------------------------------------------------------------
extern "C" void kernel_launch(void* const* d_in, const int* in_sizes, int n_in,
                              void* d_out, int out_size) {
    const float* x      = (const float*)d_in[0];
    const float* coarse = (const float*)d_in[1];
    const float* sigma  = (const float*)d_in[2];
    const float* wfeat  = (const float*)d_in[3];
    const float* wfuse  = (const float*)d_in[4];
    const float* gamma  = (const float*)d_in[5];
    const float* beta   = (const float*)d_in[6];
    const float* mean   = (const float*)d_in[7];
    const float* var    = (const float*)d_in[8];
    float* out = (float*)d_out;

    float* bias;
    unsigned *wa1, *wa2, *xpk, *msgpk, *aggpk;
    cudaGetSymbolAddress((void**)&wa1,   g_wa1pk);
    cudaGetSymbolAddress((void**)&wa2,   g_wa2pk);
    cudaGetSymbolAddress((void**)&xpk,   g_xpk);
    cudaGetSymbolAddress((void**)&bias,  g_bias);
    cudaGetSymbolAddress((void**)&msgpk, g_msgpk);
    cudaGetSymbolAddress((void**)&aggpk, g_aggpk);

    // affinity + weight rearrange (bf16) + x packing (bf16) + bias
    front_kernel<<<1164, 160>>>(x, coarse, sigma, wfeat, wfuse,
                                gamma, beta, mean, var);
    // messages = w' @ x + bias  (bf16 MMA; packed bf16x2 output)
    gemm1_kernel<<<dim3(HW / GBN, C_ / GBM), 256>>>(wa1, xpk, msgpk, bias);
    // spatially-varying 7x7 aggregation -> packed adjacent-channel bf16x2
    agg_kernel<<<dim3(H_, C_ / 64), dim3(20, 16)>>>();
    // out = x + w_fuse @ agg  (bf16 MMA, fp32 resid epilogue)
    gemm2_kernel<<<dim3(HW / GBN, C_ / GBM), 256>>>(wa2, aggpk, out, x);
}

// round 17
// speedup vs baseline: 2.2093x; 1.0009x over previous
#include <cuda_runtime.h>
#include <cuda_bf16.h>
#include <math.h>

#define H_  80
#define W_  80
#define HW  6400
#define C_  256
#define CP  19
#define KS  7
#define K2  49

// Scratch (allocation-free: __device__ globals)
__device__ float    g_bias[C_];          // BN-folded bias for w_feat
__device__ unsigned g_wa1pk[16*16*32*4]; // bf16x2 fragment-ordered BN-folded w_feat
__device__ unsigned g_wa2pk[16*16*32*4]; // bf16x2 fragment-ordered w_fuse
__device__ unsigned g_xpk[128 * HW];     // x packed bf16x2 (channels 2k, 2k+1)
__device__ unsigned g_msgpk[128 * HW];   // messages bf16x2 pairs (c, c+8)
__device__ unsigned g_aggpk[128 * HW];   // agg bf16x2 adjacent pairs (2k, 2k+1)
__device__ float    g_aff[K2 * HW];      // unnormalized affinity

// ---------------------------------------------------------------------------
// Front kernel: blockIdx-partitioned union of
//   [0,140)     affinity taps
//   [140,652)   weight rearrange -> bf16x2 m16n8k16 A-fragments
//   [652,908)   x packing -> bf16x2 adjacent-channel pairs
//   [908,1164)  BN-folded bias reduction
// ---------------------------------------------------------------------------
__global__ void __launch_bounds__(160) front_kernel(
        const float* __restrict__ x,
        const float* __restrict__ coarse, const float* __restrict__ sigma,
        const float* __restrict__ wfeat,  const float* __restrict__ wfuse,
        const float* __restrict__ gamma,  const float* __restrict__ beta,
        const float* __restrict__ mean,   const float* __restrict__ var) {
    int b = blockIdx.x;
    int t = threadIdx.x;

    if (b < 140) {
        // ---- affinity: 2 pixels per thread, sliding window ----
        int tx = t % 40;                  // pixels 2tx, 2tx+1
        int h  = (b % 20) * 4 + t / 40;
        int i  = b / 20;                  // tap row 0..6
        int b0 = tx * 2;

        float sr = fmaxf(sigma[0], 0.0f);
        float invd = 1.0f / (2.0f * sr * sr + 1e-8f);

        int hh = h + i - 3;
        bool rowok = (hh >= 0) && (hh < H_);
        const float* crow = coarse + h * W_;
        const float* nrow = coarse + (rowok ? hh : 0) * W_;

        bool v[5];
#pragma unroll
        for (int l = 0; l < 5; l++) {
            int col = b0 - 4 + 2 * l;
            v[l] = rowok && (col >= 0) && (col <= W_ - 2);
        }

        float d[KS][2];
#pragma unroll
        for (int j = 0; j < KS; j++) { d[j][0] = 0.0f; d[j][1] = 0.0f; }

        const float2 z2 = make_float2(0.0f, 0.0f);
#pragma unroll
        for (int cp = 0; cp < CP; cp++) {
            float2 cen = *(const float2*)(crow + cp * HW + b0);
            const float* nb = nrow + cp * HW;
            float win[8];
            float2 L;
            L = v[0] ? *(const float2*)(nb + b0 - 4) : z2; win[0] = L.y;
            L = v[1] ? *(const float2*)(nb + b0 - 2) : z2; win[1] = L.x; win[2] = L.y;
            L = v[2] ? *(const float2*)(nb + b0)     : z2; win[3] = L.x; win[4] = L.y;
            L = v[3] ? *(const float2*)(nb + b0 + 2) : z2; win[5] = L.x; win[6] = L.y;
            L = v[4] ? *(const float2*)(nb + b0 + 4) : z2; win[7] = L.x;
#pragma unroll
            for (int j = 0; j < KS; j++) {
                float t0 = win[j]     - cen.x; d[j][0] += t0 * t0;
                float t1 = win[j + 1] - cen.y; d[j][1] += t1 * t1;
            }
        }

        int p = h * W_ + b0;
#pragma unroll
        for (int j = 0; j < KS; j++) {
            g_aff[(i * KS + j) * HW + p]     = __expf(__expf(-d[j][0] * invd));
            g_aff[(i * KS + j) * HW + p + 1] = __expf(__expf(-d[j][1] * invd));
        }
    } else if (b < 652) {
        // ---- weight rearrange -> bf16 fragments ----
        if (t < 128) {
            int bb = b - 140;
            int w2 = bb >> 8;             // 0: wfeat (scaled), 1: wfuse
            bb &= 255;
            int kb16 = bb & 15, mb = bb >> 4;
            int lane = t & 31, q = t >> 5;
            int gid = lane >> 2, tig = lane & 3;
            int row = mb * 16 + gid + (q & 1) * 8;
            int k0  = kb16 * 16 + tig * 2 + (q >> 1) * 8;
            const float* src = w2 ? wfuse : wfeat;
            float v0 = src[row * C_ + k0];
            float v1 = src[row * C_ + k0 + 1];
            if (!w2) {
                v0 *= gamma[k0]     * rsqrtf(var[k0]     + 1e-5f);
                v1 *= gamma[k0 + 1] * rsqrtf(var[k0 + 1] + 1e-5f);
            }
            __nv_bfloat162 w = __floats2bfloat162_rn(v0, v1);
            unsigned* dst = w2 ? g_wa2pk : g_wa1pk;
            dst[((kb16 * 16 + mb) * 32 + lane) * 4 + q] =
                *reinterpret_cast<unsigned*>(&w);
        }
    } else if (b < 908) {
        // ---- x packing: row kp holds bf16x2 (x[2kp], x[2kp+1]) ----
        int b2 = b - 652;                 // 0..255
        int kp = b2 >> 1;
        int base = (b2 & 1) * 3200;
        const float* x0 = x + (2 * kp) * HW;
        const float* x1 = x + (2 * kp + 1) * HW;
        unsigned* dst = g_xpk + kp * HW;
        for (int idx = t; idx < 3200; idx += 160) {
            int p = base + idx;
            __nv_bfloat162 w = __floats2bfloat162_rn(x0[p], x1[p]);
            dst[p] = *reinterpret_cast<unsigned*>(&w);
        }
    } else {
        // ---- bias reduction ----
        int o = b - 908;                  // 0..255
        float s = 0.0f;
        for (int c = t; c < C_; c += 160) {
            float a = gamma[c] * rsqrtf(var[c] + 1e-5f);
            s += wfeat[o * C_ + c] * (beta[c] - mean[c] * a);
        }
#pragma unroll
        for (int off = 16; off; off >>= 1) s += __shfl_xor_sync(~0u, s, off);
        __shared__ float red[5];
        if ((t & 31) == 0) red[t >> 5] = s;
        __syncthreads();
        if (t == 0) g_bias[o] = red[0] + red[1] + red[2] + red[3] + red[4];
    }
}

// ---------------------------------------------------------------------------
// bf16 m16n8k16 GEMM body, BK=64 (4 mainloop iterations: half the barrier
// rendezvous of BK=32, prefetch-ahead covers ~520 cyc). A-frags: one LDG.128
// per (k16, mi). B: packed bf16x2 rows via 3-stage cp.async (8KB/stage).
// Tile 64x64, 8 warps (2x4), warp 32x16.
// ---------------------------------------------------------------------------
#define GBM 64
#define GBN 64
#define GBK 64
#define BSTR2 72
#define NSTG 3

__device__ __forceinline__ void cp16(void* smem, const void* gmem) {
    unsigned s = (unsigned)__cvta_generic_to_shared(smem);
    asm volatile("cp.async.ca.shared.global [%0], [%1], 16;\n" :: "r"(s), "l"(gmem));
}

__device__ __forceinline__ void mma_bf16(float* c, const unsigned* a, const unsigned* b) {
    asm volatile(
        "mma.sync.aligned.m16n8k16.row.col.f32.bf16.bf16.f32 "
        "{%0,%1,%2,%3}, {%4,%5,%6,%7}, {%8,%9}, {%0,%1,%2,%3};\n"
        : "+f"(c[0]), "+f"(c[1]), "+f"(c[2]), "+f"(c[3])
        : "r"(a[0]), "r"(a[1]), "r"(a[2]), "r"(a[3]), "r"(b[0]), "r"(b[1]));
}

__device__ __forceinline__ void gemm_body_bf16(
        int bx, int by,
        const unsigned* __restrict__ Afrag,   // [16][16][32][4] bf16x2 words
        const unsigned* __restrict__ Bpk,     // [128][HW] packed (2k, 2k+1)
        float* __restrict__ Cout,
        unsigned* __restrict__ msgpk,
        const float* __restrict__ bias,
        const float* __restrict__ resid) {
    __shared__ __align__(16) unsigned Bs[NSTG][32][BSTR2];
    const int N = HW;

    int t    = threadIdx.x;
    int warp = t >> 5, lane = t & 31;
    int gid  = lane >> 2, tig = lane & 3;
    int wm   = warp >> 2, wn = warp & 3;
    int m0   = by * GBM, n0 = bx * GBN;
    int mb0  = by * 4 + wm * 2;

    int prow = t >> 4;             // 0..15; thread also loads prow+16
    int pco  = (t & 15) * 4;

    float acc[2][2][4];
#pragma unroll
    for (int mi = 0; mi < 2; mi++)
#pragma unroll
        for (int ni = 0; ni < 2; ni++)
#pragma unroll
            for (int q = 0; q < 4; q++) acc[mi][ni][q] = 0.0f;

#define LOADBP(s, k0)                                                         \
    {                                                                          \
        cp16(&Bs[s][prow][pco],      Bpk + (((k0) >> 1) + prow) * N + n0 + pco);      \
        cp16(&Bs[s][prow + 16][pco], Bpk + (((k0) >> 1) + prow + 16) * N + n0 + pco); \
        asm volatile("cp.async.commit_group;\n");                              \
    }

    LOADBP(0, 0);
    LOADBP(1, GBK);

    const int NIT = C_ / GBK;   // 4
    for (int it = 0; it < NIT; it++) {
        if (it + 1 < NIT) asm volatile("cp.async.wait_group 1;\n");
        else              asm volatile("cp.async.wait_group 0;\n");
        __syncthreads();
        if (it + 2 < NIT) LOADBP((it + 2) % NSTG, (it + 2) * GBK);

        int s = it % NSTG;
#pragma unroll
        for (int kk = 0; kk < 4; kk++) {          // four k16 blocks per iter
            int kbg16 = it * 4 + kk;
            uint4 a0 = *(const uint4*)(Afrag + ((kbg16 * 16 + mb0) * 32 + lane) * 4);
            uint4 a1 = *(const uint4*)(Afrag + ((kbg16 * 16 + mb0 + 1) * 32 + lane) * 4);
            unsigned aR[2][4] = {{a0.x, a0.y, a0.z, a0.w},
                                 {a1.x, a1.y, a1.z, a1.w}};
            unsigned bR[2][2];
#pragma unroll
            for (int ni = 0; ni < 2; ni++) {
                int cN = wn * 16 + ni * 8 + gid;
                bR[ni][0] = Bs[s][kk * 8 + tig][cN];      // (k=2tig, 2tig+1)
                bR[ni][1] = Bs[s][kk * 8 + tig + 4][cN];  // (k=2tig+8, +9)
            }
#pragma unroll
            for (int mi = 0; mi < 2; mi++)
#pragma unroll
                for (int ni = 0; ni < 2; ni++)
                    mma_bf16(acc[mi][ni], aR[mi], bR[ni]);
        }
        __syncthreads();
    }

#pragma unroll
    for (int mi = 0; mi < 2; mi++) {
        int r0 = m0 + wm * 32 + mi * 16 + gid;
        int r1 = r0 + 8;
#pragma unroll
        for (int ni = 0; ni < 2; ni++) {
            int col = n0 + wn * 16 + ni * 8 + tig * 2;
            if (msgpk) {
                float b0v = bias[r0];
                float b1v = bias[r1];
                int pid = (mb0 + mi) * 8 + gid;
                __nv_bfloat162 w0 = __floats2bfloat162_rn(acc[mi][ni][0] + b0v,
                                                          acc[mi][ni][2] + b1v);
                __nv_bfloat162 w1 = __floats2bfloat162_rn(acc[mi][ni][1] + b0v,
                                                          acc[mi][ni][3] + b1v);
                uint2 pk;
                pk.x = *reinterpret_cast<unsigned*>(&w0);
                pk.y = *reinterpret_cast<unsigned*>(&w1);
                *(uint2*)(msgpk + pid * N + col) = pk;
            } else {
                float2 rv0 = *(const float2*)(resid + r0 * N + col);
                float2 rv1 = *(const float2*)(resid + r1 * N + col);
                float2 v0, v1;
                v0.x = acc[mi][ni][0] + rv0.x;
                v0.y = acc[mi][ni][1] + rv0.y;
                v1.x = acc[mi][ni][2] + rv1.x;
                v1.y = acc[mi][ni][3] + rv1.y;
                *(float2*)(Cout + r0 * N + col) = v0;
                *(float2*)(Cout + r1 * N + col) = v1;
            }
        }
    }
#undef LOADBP
}

__global__ void __launch_bounds__(256) gemm1_kernel(
        const unsigned* __restrict__ Afrag, const unsigned* __restrict__ Bpk,
        unsigned* __restrict__ msgpk,       const float* __restrict__ bias) {
    gemm_body_bf16(blockIdx.x, blockIdx.y, Afrag, Bpk,
                   nullptr, msgpk, bias, nullptr);
}

__global__ void __launch_bounds__(256) gemm2_kernel(
        const unsigned* __restrict__ Afrag, const unsigned* __restrict__ Bpk,
        float* __restrict__ Cout,           const float* __restrict__ resid) {
    gemm_body_bf16(blockIdx.x, blockIdx.y, Afrag, Bpk,
                   Cout, nullptr, nullptr, resid);
}

// ---------------------------------------------------------------------------
// Aggregation: 4 pixels x 2 pids per thread, pid pair {p0, p0+1} (p0 even)
// -> packed output rows kp hold (2kp, 2kp+1), the m16n8k16 B pairing.
// Block (20,16)=320 thr, grid (80,4).
// ---------------------------------------------------------------------------
__global__ void __launch_bounds__(320) agg_kernel() {
    int h  = blockIdx.x;                       // 0..79
    int tx = threadIdx.x;                      // 0..19 -> pixels 4tx..4tx+3
    int ty = threadIdx.y;                      // 0..15
    int B16 = blockIdx.y * 4 + (ty >> 2);      // 16-channel block
    int g   = ty & 3;
    int p0  = B16 * 8 + g * 2;                 // pids p0, p0+1

    __shared__ __align__(16) float saff[K2][W_];
    __shared__ __align__(16) float sinv[W_];
    int tid = ty * 20 + tx;
    const float* affrow = g_aff + h * W_;
    for (int idx = tid; idx < K2 * W_; idx += 320) {
        int k2 = idx / W_;
        int ww = idx - k2 * W_;
        saff[k2][ww] = affrow[k2 * HW + ww];
    }
    __syncthreads();
    if (tid < W_) {
        float s = 0.0f;
#pragma unroll
        for (int k = 0; k < K2; k++) s += saff[k][tid];
        sinv[tid] = 1.0f / s;
    }
    __syncthreads();

    float2 acc[4][2];   // [px][pr]: x = lo channel of pid, y = hi channel
#pragma unroll
    for (int px = 0; px < 4; px++)
#pragma unroll
        for (int pr = 0; pr < 2; pr++) acc[px][pr] = make_float2(0.f, 0.f);

    const uint4 z4 = make_uint4(0u, 0u, 0u, 0u);
    bool haveA = (tx > 0), haveC = (tx < 19);

    for (int i = 0; i < KS; i++) {
        int hh = h + i - 3;
        if (hh < 0 || hh >= H_) continue;

        float4 s[KS];
#pragma unroll
        for (int j = 0; j < KS; j++)
            s[j] = *(const float4*)&saff[i * KS + j][tx * 4];

#pragma unroll
        for (int pr = 0; pr < 2; pr++) {
            const unsigned* mrow = g_msgpk + (p0 + pr) * HW + hh * W_;
            uint4 va = haveA ? *(const uint4*)(mrow + tx * 4 - 4) : z4;
            uint4 vb = *(const uint4*)(mrow + tx * 4);
            uint4 vc = haveC ? *(const uint4*)(mrow + tx * 4 + 4) : z4;
            unsigned wd[10] = {va.y, va.z, va.w,
                               vb.x, vb.y, vb.z, vb.w,
                               vc.x, vc.y, vc.z};
            float wl[10], wh[10];
#pragma unroll
            for (int q = 0; q < 10; q++) {
                wl[q] = __uint_as_float(wd[q] << 16);
                wh[q] = __uint_as_float(wd[q] & 0xFFFF0000u);
            }
#pragma unroll
            for (int j = 0; j < KS; j++) {
                acc[0][pr].x += wl[j + 0] * s[j].x;
                acc[0][pr].y += wh[j + 0] * s[j].x;
                acc[1][pr].x += wl[j + 1] * s[j].y;
                acc[1][pr].y += wh[j + 1] * s[j].y;
                acc[2][pr].x += wl[j + 2] * s[j].z;
                acc[2][pr].y += wh[j + 2] * s[j].z;
                acc[3][pr].x += wl[j + 3] * s[j].w;
                acc[3][pr].y += wh[j + 3] * s[j].w;
            }
        }
    }

    float4 si = *(const float4*)&sinv[tx * 4];
    float sv[4] = {si.x, si.y, si.z, si.w};
    int kp_lo = B16 * 8 + g;
    int kp_hi = kp_lo + 4;
    uint4 w0, w1;
    unsigned* w0p = &w0.x;
    unsigned* w1p = &w1.x;
#pragma unroll
    for (int px = 0; px < 4; px++) {
        __nv_bfloat162 lo = __floats2bfloat162_rn(acc[px][0].x * sv[px],
                                                  acc[px][1].x * sv[px]);
        __nv_bfloat162 hi = __floats2bfloat162_rn(acc[px][0].y * sv[px],
                                                  acc[px][1].y * sv[px]);
        w0p[px] = *reinterpret_cast<unsigned*>(&lo);
        w1p[px] = *reinterpret_cast<unsigned*>(&hi);
    }
    *(uint4*)(g_aggpk + kp_lo * HW + h * W_ + tx * 4) = w0;
    *(uint4*)(g_aggpk + kp_hi * HW + h * W_ + tx * 4) = w1;
}

// ---------------------------------------------------------------------------
// Launch
// ---------------------------------------------------------------------------
extern "C" void kernel_launch(void* const* d_in, const int* in_sizes, int n_in,
                              void* d_out, int out_size) {
    const float* x      = (const float*)d_in[0];
    const float* coarse = (const float*)d_in[1];
    const float* sigma  = (const float*)d_in[2];
    const float* wfeat  = (const float*)d_in[3];
    const float* wfuse  = (const float*)d_in[4];
    const float* gamma  = (const float*)d_in[5];
    const float* beta   = (const float*)d_in[6];
    const float* mean   = (const float*)d_in[7];
    const float* var    = (const float*)d_in[8];
    float* out = (float*)d_out;

    float* bias;
    unsigned *wa1, *wa2, *xpk, *msgpk, *aggpk;
    cudaGetSymbolAddress((void**)&wa1,   g_wa1pk);
    cudaGetSymbolAddress((void**)&wa2,   g_wa2pk);
    cudaGetSymbolAddress((void**)&xpk,   g_xpk);
    cudaGetSymbolAddress((void**)&bias,  g_bias);
    cudaGetSymbolAddress((void**)&msgpk, g_msgpk);
    cudaGetSymbolAddress((void**)&aggpk, g_aggpk);

    // affinity + weight rearrange (bf16) + x packing (bf16) + bias
    front_kernel<<<1164, 160>>>(x, coarse, sigma, wfeat, wfuse,
                                gamma, beta, mean, var);
    // messages = w' @ x + bias  (bf16 MMA; packed bf16x2 output)
    gemm1_kernel<<<dim3(HW / GBN, C_ / GBM), 256>>>(wa1, xpk, msgpk, bias);
    // spatially-varying 7x7 aggregation -> packed adjacent-channel bf16x2
    agg_kernel<<<dim3(H_, C_ / 64), dim3(20, 16)>>>();
    // out = x + w_fuse @ agg  (bf16 MMA, fp32 resid epilogue)
    gemm2_kernel<<<dim3(HW / GBN, C_ / GBM), 256>>>(wa2, aggpk, out, x);
}